// round 10
// baseline (speedup 1.0000x reference)
#include <cuda_runtime.h>
#include <cuda_bf16.h>
#include <cstdint>

#define N_NODES 100000
#define N_EDGES 1600000
#define HID 128

// ---------------- scratch (device globals; no allocation) ----------------
__device__ float g_cnt [N_NODES];
__device__ float g_agg1[N_NODES * 6];
__device__ float g_h1  [N_NODES * HID];
__device__ float g_agg2[N_NODES * HID];
__device__ float g_p   [N_NODES * HID];   // h2 @ W_e1[0:128]
__device__ float g_q   [N_NODES * HID];   // h2 @ W_e1[128:256]

// ---------------- warp MMA helpers (baseline PTX) ----------------
__device__ __forceinline__ uint32_t smem_u32(const void* p) {
    uint32_t a;
    asm("{ .reg .u64 t; cvta.to.shared.u64 t, %1; cvt.u32.u64 %0, t; }" : "=r"(a) : "l"(p));
    return a;
}
__device__ __forceinline__ void mma16816(float* d, const uint32_t* a, const uint32_t* b) {
    asm volatile(
        "mma.sync.aligned.m16n8k16.row.col.f32.bf16.bf16.f32 "
        "{%0,%1,%2,%3}, {%4,%5,%6,%7}, {%8,%9}, {%0,%1,%2,%3};"
        : "+f"(d[0]), "+f"(d[1]), "+f"(d[2]), "+f"(d[3])
        : "r"(a[0]), "r"(a[1]), "r"(a[2]), "r"(a[3]), "r"(b[0]), "r"(b[1]));
}
__device__ __forceinline__ void ldsm4(uint32_t* r, uint32_t addr) {
    asm volatile("ldmatrix.sync.aligned.m8n8.x4.shared.b16 {%0,%1,%2,%3}, [%4];"
                 : "=r"(r[0]), "=r"(r[1]), "=r"(r[2]), "=r"(r[3]) : "r"(addr));
}
__device__ __forceinline__ uint32_t pack_bf16(float x, float y) {
    __nv_bfloat16 bx = __float2bfloat16(x), by = __float2bfloat16(y);
    return ((uint32_t)__bfloat16_as_ushort(by) << 16) | __bfloat16_as_ushort(bx);
}

// ---------------- zero scratch accumulators ----------------
__global__ void k_zero() {
    int i = blockIdx.x * 256 + threadIdx.x;
    float4 z = make_float4(0.f, 0.f, 0.f, 0.f);
    if (i < N_NODES * HID / 4) reinterpret_cast<float4*>(g_agg2)[i] = z;
    if (i < N_NODES * 6 / 4)   reinterpret_cast<float4*>(g_agg1)[i] = z;
    if (i < N_NODES / 4)       reinterpret_cast<float4*>(g_cnt)[i]  = z;
}

// ---------------- SAGE layer 1 scatter ----------------
__global__ void k_agg1(const float* __restrict__ x, const int* __restrict__ ei) {
    int e = blockIdx.x * 256 + threadIdx.x;
    int s = ei[e];
    int d = ei[N_EDGES + e];
    atomicAdd(&g_cnt[d], 1.0f);
    const float2* xr = reinterpret_cast<const float2*>(x + s * 6);
    float* dst = &g_agg1[d * 6];
#pragma unroll
    for (int k = 0; k < 3; k++) {
        float2 v = xr[k];
        asm volatile("red.global.add.v2.f32 [%0], {%1, %2};"
                     :: "l"(dst + k * 2), "f"(v.x), "f"(v.y) : "memory");
    }
}

// ---------------- h1 = relu(x@W1r + mean1@W1n + b1) ----------------
__global__ void k_h1(const float* __restrict__ x,
                     const float* __restrict__ w1r, const float* __restrict__ w1n,
                     const float* __restrict__ b1) {
    int t = threadIdx.x;
    int node = blockIdx.x * 2 + (t >> 7);
    int j = t & 127;
    float inv = 1.0f / fmaxf(g_cnt[node], 1.0f);
    float acc = b1[j];
#pragma unroll
    for (int k = 0; k < 6; k++) {
        acc += x[node * 6 + k] * w1r[k * 128 + j]
             + g_agg1[node * 6 + k] * inv * w1n[k * 128 + j];
    }
    g_h1[node * 128 + j] = fmaxf(acc, 0.f);
}

// ---------------- scatter h1[src] into agg2 (vector red) ----------------
__global__ void k_agg2(const int* __restrict__ ei) {
    int w = blockIdx.x * 8 + (threadIdx.x >> 5);
    int lane = threadIdx.x & 31;
    int s = ei[w];
    int d = ei[N_EDGES + w];
    float4 v = *reinterpret_cast<const float4*>(&g_h1[s * 128 + lane * 4]);
    float* dst = &g_agg2[d * 128 + lane * 4];
    asm volatile("red.global.add.v4.f32 [%0], {%1, %2, %3, %4};"
                 :: "l"(dst), "f"(v.x), "f"(v.y), "f"(v.z), "f"(v.w) : "memory");
}

// ============== k_npq: h2 + p/q via HMMA, 64-row tiles, 2 CTAs/SM =============
// Per tile (64 nodes):
//   acc  = h1_tile @ W2r + mean_tile @ W2n      (2 K=128 passes)
//   h2   = relu(acc + b2) -> bf16 split, written back into A smem
//   p    = h2 @ Wa ; q = h2 @ Wb                (2 more passes)
// bf16 2-term error split (3 mma terms) throughout; layout/mappings identical
// to k_edge_mma (AROW=136 padded rows, same ldsm fragment addressing).
#define NR2 136                      // padded row elems (272 B)
#define SMN_AHI 0                    // 64 rows  * 272 = 17408
#define SMN_ALO 17408
#define SMN_BHI 34816                // 128 rows * 272 = 34816
#define SMN_BLO 69632
#define SMN_B2  104448               // float[128]
#define SMN_TOTAL 104960
#define N_TILES2 ((N_NODES + 63) / 64)
#define NPQ_GRID 296

__global__ __launch_bounds__(256, 2)
void k_npq(const float* __restrict__ w2r, const float* __restrict__ w2n,
           const float* __restrict__ b2, const float* __restrict__ we1) {
    extern __shared__ __align__(16) char smem[];
    uint32_t smem_base = smem_u32(smem);
    int t = threadIdx.x;
    int wid = t >> 5, lane = t & 31;
    int wm = wid >> 2;               // 0..1 : rows wm*32..+31
    int wn = wid & 3;                // 0..3 : cols wn*32..+31

    float* b2s = (float*)(smem + SMN_B2);
    if (t < 128) b2s[t] = b2[t];

    int lrow = (lane & 7) + ((lane & 8) ? 8 : 0);
    int lcol = (lane & 16) ? 8 : 0;
    int b_nrow = wn * 32 + ((lane >> 4) << 3) + (lane & 7);
    int b_khalf = (lane >> 3) & 1;
    uint32_t b_base = (uint32_t)b_nrow * (NR2 * 2) + (uint32_t)b_khalf * 16;

    for (int tile = blockIdx.x; tile < N_TILES2; tile += NPQ_GRID) {
        int row0 = tile * 64;
        float acc[2][4][4];
#pragma unroll
        for (int mi = 0; mi < 2; mi++)
#pragma unroll
            for (int nn = 0; nn < 4; nn++)
#pragma unroll
                for (int r = 0; r < 4; r++) acc[mi][nn][r] = 0.f;

#pragma unroll 1
        for (int kc = 0; kc < 2; kc++) {
            // stage A chunk: 64 rows, warp-per-row
#pragma unroll
            for (int i = 0; i < 8; i++) {
                int row = i * 8 + wid;
                int grow = row0 + row;
                float v[4] = {0.f, 0.f, 0.f, 0.f};
                if (grow < N_NODES) {
                    const float* src = kc ? &g_agg2[grow * 128] : &g_h1[grow * 128];
                    float4 a = *reinterpret_cast<const float4*>(&src[lane * 4]);
                    float sc = kc ? (1.0f / fmaxf(g_cnt[grow], 1.0f)) : 1.0f;
                    v[0] = a.x * sc; v[1] = a.y * sc; v[2] = a.z * sc; v[3] = a.w * sc;
                }
                float hv[4];
#pragma unroll
                for (int j = 0; j < 4; j++) hv[j] = __bfloat162float(__float2bfloat16(v[j]));
                uint2 hp, lp;
                hp.x = pack_bf16(hv[0], hv[1]); hp.y = pack_bf16(hv[2], hv[3]);
                lp.x = pack_bf16(v[0] - hv[0], v[1] - hv[1]);
                lp.y = pack_bf16(v[2] - hv[2], v[3] - hv[3]);
                uint32_t off = (uint32_t)row * (NR2 * 2) + (uint32_t)(lane * 4) * 2;
                *(uint2*)(smem + SMN_AHI + off) = hp;
                *(uint2*)(smem + SMN_ALO + off) = lp;
            }
            // stage B chunk: BT[n][k] = W[k*128+n], 128 rows
            {
                const float* W = kc ? w2n : w2r;
#pragma unroll
                for (int i = 0; i < 16; i++) {
                    int idx = i * 256 + t;
                    int k = idx >> 5;
                    int n4 = (idx & 31) * 4;
                    float4 w = *reinterpret_cast<const float4*>(&W[k * 128 + n4]);
                    float wv[4] = {w.x, w.y, w.z, w.w};
#pragma unroll
                    for (int j = 0; j < 4; j++) {
                        float h = __bfloat162float(__float2bfloat16(wv[j]));
                        uint32_t off = (uint32_t)(n4 + j) * (NR2 * 2) + (uint32_t)k * 2;
                        *(__nv_bfloat16*)(smem + SMN_BHI + off) = __float2bfloat16(h);
                        *(__nv_bfloat16*)(smem + SMN_BLO + off) = __float2bfloat16(wv[j] - h);
                    }
                }
            }
            __syncthreads();
            // MMA K=128 accumulate
#pragma unroll
            for (int kk = 0; kk < 8; kk++) {
                uint32_t ahi[2][4], alo[2][4];
                uint32_t aoff = (uint32_t)(wm * 32 + lrow) * (NR2 * 2)
                              + (uint32_t)(kk * 16 + lcol) * 2;
                ldsm4(ahi[0], smem_base + SMN_AHI + aoff);
                ldsm4(ahi[1], smem_base + SMN_AHI + aoff + 16 * (NR2 * 2));
                ldsm4(alo[0], smem_base + SMN_ALO + aoff);
                ldsm4(alo[1], smem_base + SMN_ALO + aoff + 16 * (NR2 * 2));
                uint32_t bh01[4], bh23[4], bl01[4], bl23[4];
                uint32_t boff = b_base + (uint32_t)kk * 32;
                ldsm4(bh01, smem_base + SMN_BHI + boff);
                ldsm4(bh23, smem_base + SMN_BHI + boff + 16 * (NR2 * 2));
                ldsm4(bl01, smem_base + SMN_BLO + boff);
                ldsm4(bl23, smem_base + SMN_BLO + boff + 16 * (NR2 * 2));
                uint32_t* bh[4] = {bh01, bh01 + 2, bh23, bh23 + 2};
                uint32_t* bl[4] = {bl01, bl01 + 2, bl23, bl23 + 2};
#pragma unroll
                for (int mi = 0; mi < 2; mi++) {
#pragma unroll
                    for (int nn = 0; nn < 4; nn++) {
                        mma16816(acc[mi][nn], ahi[mi], bh[nn]);
                        mma16816(acc[mi][nn], ahi[mi], bl[nn]);
                        mma16816(acc[mi][nn], alo[mi], bh[nn]);
                    }
                }
            }
            __syncthreads();
        }

        // h2 = relu(acc + b2) -> split back into A smem
#pragma unroll
        for (int mi = 0; mi < 2; mi++) {
#pragma unroll
            for (int nn = 0; nn < 4; nn++) {
#pragma unroll
                for (int rp = 0; rp < 2; rp++) {
                    int row = wm * 32 + mi * 16 + (lane >> 2) + rp * 8;
                    int col = wn * 32 + nn * 8 + (lane & 3) * 2;
                    float v0 = fmaxf(acc[mi][nn][rp * 2 + 0] + b2s[col], 0.f);
                    float v1 = fmaxf(acc[mi][nn][rp * 2 + 1] + b2s[col + 1], 0.f);
                    float h0 = __bfloat162float(__float2bfloat16(v0));
                    float h1 = __bfloat162float(__float2bfloat16(v1));
                    uint32_t off = (uint32_t)row * (NR2 * 2) + (uint32_t)col * 2;
                    *(uint32_t*)(smem + SMN_AHI + off) = pack_bf16(h0, h1);
                    *(uint32_t*)(smem + SMN_ALO + off) = pack_bf16(v0 - h0, v1 - h1);
                }
            }
        }
        __syncthreads();

        // p = h2@Wa ; q = h2@Wb
#pragma unroll 1
        for (int nc = 0; nc < 2; nc++) {
            const float* W = we1 + nc * 128 * 128;
#pragma unroll
            for (int i = 0; i < 16; i++) {
                int idx = i * 256 + t;
                int k = idx >> 5;
                int n4 = (idx & 31) * 4;
                float4 w = *reinterpret_cast<const float4*>(&W[k * 128 + n4]);
                float wv[4] = {w.x, w.y, w.z, w.w};
#pragma unroll
                for (int j = 0; j < 4; j++) {
                    float h = __bfloat162float(__float2bfloat16(wv[j]));
                    uint32_t off = (uint32_t)(n4 + j) * (NR2 * 2) + (uint32_t)k * 2;
                    *(__nv_bfloat16*)(smem + SMN_BHI + off) = __float2bfloat16(h);
                    *(__nv_bfloat16*)(smem + SMN_BLO + off) = __float2bfloat16(wv[j] - h);
                }
            }
            __syncthreads();

            float acc2[2][4][4];
#pragma unroll
            for (int mi = 0; mi < 2; mi++)
#pragma unroll
                for (int nn = 0; nn < 4; nn++)
#pragma unroll
                    for (int r = 0; r < 4; r++) acc2[mi][nn][r] = 0.f;

#pragma unroll
            for (int kk = 0; kk < 8; kk++) {
                uint32_t ahi[2][4], alo[2][4];
                uint32_t aoff = (uint32_t)(wm * 32 + lrow) * (NR2 * 2)
                              + (uint32_t)(kk * 16 + lcol) * 2;
                ldsm4(ahi[0], smem_base + SMN_AHI + aoff);
                ldsm4(ahi[1], smem_base + SMN_AHI + aoff + 16 * (NR2 * 2));
                ldsm4(alo[0], smem_base + SMN_ALO + aoff);
                ldsm4(alo[1], smem_base + SMN_ALO + aoff + 16 * (NR2 * 2));
                uint32_t bh01[4], bh23[4], bl01[4], bl23[4];
                uint32_t boff = b_base + (uint32_t)kk * 32;
                ldsm4(bh01, smem_base + SMN_BHI + boff);
                ldsm4(bh23, smem_base + SMN_BHI + boff + 16 * (NR2 * 2));
                ldsm4(bl01, smem_base + SMN_BLO + boff);
                ldsm4(bl23, smem_base + SMN_BLO + boff + 16 * (NR2 * 2));
                uint32_t* bh[4] = {bh01, bh01 + 2, bh23, bh23 + 2};
                uint32_t* bl[4] = {bl01, bl01 + 2, bl23, bl23 + 2};
#pragma unroll
                for (int mi = 0; mi < 2; mi++) {
#pragma unroll
                    for (int nn = 0; nn < 4; nn++) {
                        mma16816(acc2[mi][nn], ahi[mi], bh[nn]);
                        mma16816(acc2[mi][nn], ahi[mi], bl[nn]);
                        mma16816(acc2[mi][nn], alo[mi], bh[nn]);
                    }
                }
            }

            float* dst = nc ? g_q : g_p;
#pragma unroll
            for (int mi = 0; mi < 2; mi++) {
#pragma unroll
                for (int nn = 0; nn < 4; nn++) {
#pragma unroll
                    for (int rp = 0; rp < 2; rp++) {
                        int row = wm * 32 + mi * 16 + (lane >> 2) + rp * 8;
                        int grow = row0 + row;
                        if (grow < N_NODES) {
                            int col = wn * 32 + nn * 8 + (lane & 3) * 2;
                            float2 v = make_float2(acc2[mi][nn][rp * 2 + 0],
                                                   acc2[mi][nn][rp * 2 + 1]);
                            *reinterpret_cast<float2*>(&dst[grow * 128 + col]) = v;
                        }
                    }
                }
            }
            __syncthreads();
        }
    }
}

// ================= edge MLP via warp HMMA (unchanged from R7) =================
#define AROW 136
#define SM_A_HI   0
#define SM_A_LO   34816
#define SM_B_HI   69632
#define SM_B_LO   87040
#define SM_PA     104448
#define SM_PB     104960
#define SM_B2S    105472
#define SM_W3S    105728
#define SM_SRC    105984
#define SM_DST    107008
#define SM_EAS    108032
#define SM_EDGE_TOTAL 112128

#define N_TILES (N_EDGES / 128)
#define EDGE_GRID 296

__global__ __launch_bounds__(256, 2)
void k_edge_mma(const int* __restrict__ ei, const float* __restrict__ ea,
                const float* __restrict__ we1, const float* __restrict__ be1,
                const float* __restrict__ we2, const float* __restrict__ be2,
                const float* __restrict__ we3, const float* __restrict__ be3,
                float* __restrict__ out) {
    extern __shared__ __align__(16) char smem[];
    uint32_t smem_base = smem_u32(smem);
    int t = threadIdx.x;
    int wid = t >> 5, lane = t & 31;
    int wm = wid >> 1;
    int wn = wid & 1;

    float* pa  = (float*)(smem + SM_PA);
    float* pb  = (float*)(smem + SM_PB);
    float* b2s = (float*)(smem + SM_B2S);
    float* w3s = (float*)(smem + SM_W3S);
    int*   srcs = (int*)(smem + SM_SRC);
    int*   dsts = (int*)(smem + SM_DST);
    float* eas  = (float*)(smem + SM_EAS);

    if (t < 64) { b2s[t] = be2[t]; w3s[t] = we3[t]; }

    int kq = lane * 4;
    float4 b1v = *reinterpret_cast<const float4*>(&be1[kq]);
    float4 wc0 = *reinterpret_cast<const float4*>(&we1[256 * 128 + kq]);
    float4 wc1 = *reinterpret_cast<const float4*>(&we1[257 * 128 + kq]);
    float4 wc2 = *reinterpret_cast<const float4*>(&we1[258 * 128 + kq]);
    float4 wc3 = *reinterpret_cast<const float4*>(&we1[259 * 128 + kq]);

    for (int idx = t; idx < 64 * 128; idx += 256) {
        int n = idx >> 7, k = idx & 127;
        float w = we2[k * 64 + n];
        float h = __bfloat162float(__float2bfloat16(w));
        uint32_t off = (uint32_t)n * (AROW * 2) + (uint32_t)k * 2;
        *(__nv_bfloat16*)(smem + SM_B_HI + off) = __float2bfloat16(h);
        *(__nv_bfloat16*)(smem + SM_B_LO + off) = __float2bfloat16(w - h);
    }
    float be3v = be3[0];

    int lrow = (lane & 7) + ((lane & 8) ? 8 : 0);
    int lcol = (lane & 16) ? 8 : 0;
    int b_nrow = wn * 32 + ((lane >> 4) << 3) + (lane & 7);
    int b_khalf = (lane >> 3) & 1;
    uint32_t b_base = (uint32_t)b_nrow * (AROW * 2) + (uint32_t)b_khalf * 16;

    int tile = blockIdx.x;
    {
        int e0 = tile * 128;
        if (t < 128) srcs[t] = ei[e0 + t];
        else         dsts[t - 128] = ei[N_EDGES + e0 + (t - 128)];
        for (int i = t; i < 512; i += 256) eas[i] = ea[e0 * 4 + i];
    }
    __syncthreads();

    int buf = 0;
    for (; tile < N_TILES; tile += EDGE_GRID) {
        int e0 = tile * 128;
        int* sb = srcs + buf * 128;
        int* db = dsts + buf * 128;
        float* eb = eas + buf * 512;

#pragma unroll 4
        for (int i = 0; i < 16; i++) {
            int edge = i * 8 + wid;
            int s = sb[edge], d = db[edge];
            float4 pv = *reinterpret_cast<const float4*>(&g_p[s * 128 + kq]);
            float4 qv = *reinterpret_cast<const float4*>(&g_q[d * 128 + kq]);
            float4 e4 = *reinterpret_cast<const float4*>(&eb[edge * 4]);
            float v[4], hv[4];
            v[0] = pv.x + qv.x + b1v.x + e4.x * wc0.x + e4.y * wc1.x + e4.z * wc2.x + e4.w * wc3.x;
            v[1] = pv.y + qv.y + b1v.y + e4.x * wc0.y + e4.y * wc1.y + e4.z * wc2.y + e4.w * wc3.y;
            v[2] = pv.z + qv.z + b1v.z + e4.x * wc0.z + e4.y * wc1.z + e4.z * wc2.z + e4.w * wc3.z;
            v[3] = pv.w + qv.w + b1v.w + e4.x * wc0.w + e4.y * wc1.w + e4.z * wc2.w + e4.w * wc3.w;
#pragma unroll
            for (int j = 0; j < 4; j++) {
                v[j] = fmaxf(v[j], 0.f);
                hv[j] = __bfloat162float(__float2bfloat16(v[j]));
            }
            uint2 hp, lp;
            hp.x = pack_bf16(hv[0], hv[1]); hp.y = pack_bf16(hv[2], hv[3]);
            lp.x = pack_bf16(v[0] - hv[0], v[1] - hv[1]);
            lp.y = pack_bf16(v[2] - hv[2], v[3] - hv[3]);
            uint32_t off = (uint32_t)edge * (AROW * 2) + (uint32_t)kq * 2;
            *(uint2*)(smem + SM_A_HI + off) = hp;
            *(uint2*)(smem + SM_A_LO + off) = lp;
        }

        int nxt = tile + EDGE_GRID;
        if (nxt < N_TILES) {
            int e0n = nxt * 128;
            int* sn = srcs + (buf ^ 1) * 128;
            int* dn = dsts + (buf ^ 1) * 128;
            float* en = eas + (buf ^ 1) * 512;
            if (t < 128) sn[t] = ei[e0n + t];
            else         dn[t - 128] = ei[N_EDGES + e0n + (t - 128)];
            for (int i = t; i < 512; i += 256) en[i] = ea[e0n * 4 + i];
        }
        __syncthreads();

        float acc[2][4][4];
#pragma unroll
        for (int mi = 0; mi < 2; mi++)
#pragma unroll
            for (int nn = 0; nn < 4; nn++)
#pragma unroll
                for (int r = 0; r < 4; r++) acc[mi][nn][r] = 0.f;

#pragma unroll
        for (int kk = 0; kk < 8; kk++) {
            uint32_t ahi[2][4], alo[2][4];
            uint32_t aoff = (uint32_t)(wm * 32 + lrow) * (AROW * 2)
                          + (uint32_t)(kk * 16 + lcol) * 2;
            ldsm4(ahi[0], smem_base + SM_A_HI + aoff);
            ldsm4(ahi[1], smem_base + SM_A_HI + aoff + 16 * (AROW * 2));
            ldsm4(alo[0], smem_base + SM_A_LO + aoff);
            ldsm4(alo[1], smem_base + SM_A_LO + aoff + 16 * (AROW * 2));

            uint32_t bh01[4], bh23[4], bl01[4], bl23[4];
            uint32_t boff = b_base + (uint32_t)kk * 32;
            ldsm4(bh01, smem_base + SM_B_HI + boff);
            ldsm4(bh23, smem_base + SM_B_HI + boff + 16 * (AROW * 2));
            ldsm4(bl01, smem_base + SM_B_LO + boff);
            ldsm4(bl23, smem_base + SM_B_LO + boff + 16 * (AROW * 2));
            uint32_t* bh[4] = {bh01, bh01 + 2, bh23, bh23 + 2};
            uint32_t* bl[4] = {bl01, bl01 + 2, bl23, bl23 + 2};

#pragma unroll
            for (int mi = 0; mi < 2; mi++) {
#pragma unroll
                for (int nn = 0; nn < 4; nn++) {
                    mma16816(acc[mi][nn], ahi[mi], bh[nn]);
                    mma16816(acc[mi][nn], ahi[mi], bl[nn]);
                    mma16816(acc[mi][nn], alo[mi], bh[nn]);
                }
            }
        }

        float part[2][2] = {{0.f, 0.f}, {0.f, 0.f}};
#pragma unroll
        for (int mi = 0; mi < 2; mi++) {
#pragma unroll
            for (int nn = 0; nn < 4; nn++) {
                int c0 = wn * 32 + nn * 8 + (lane & 3) * 2;
                float w30 = w3s[c0], w31 = w3s[c0 + 1];
                float bb0 = b2s[c0], bb1 = b2s[c0 + 1];
                part[mi][0] += fmaxf(acc[mi][nn][0] + bb0, 0.f) * w30
                             + fmaxf(acc[mi][nn][1] + bb1, 0.f) * w31;
                part[mi][1] += fmaxf(acc[mi][nn][2] + bb0, 0.f) * w30
                             + fmaxf(acc[mi][nn][3] + bb1, 0.f) * w31;
            }
        }
#pragma unroll
        for (int mi = 0; mi < 2; mi++) {
#pragma unroll
            for (int g = 0; g < 2; g++) {
                part[mi][g] += __shfl_xor_sync(0xffffffffu, part[mi][g], 1);
                part[mi][g] += __shfl_xor_sync(0xffffffffu, part[mi][g], 2);
            }
        }
        if ((lane & 3) == 0) {
            float* pw = wn ? pb : pa;
            int r0 = wm * 32 + (lane >> 2);
            pw[r0]      = part[0][0];
            pw[r0 + 8]  = part[0][1];
            pw[r0 + 16] = part[1][0];
            pw[r0 + 24] = part[1][1];
        }
        __syncthreads();
        if (t < 128) out[e0 + t] = pa[t] + pb[t] + be3v;
        buf ^= 1;
    }
}

// ---------------- launch ----------------
extern "C" void kernel_launch(void* const* d_in, const int* in_sizes, int n_in,
                              void* d_out, int out_size) {
    const float* x   = (const float*)d_in[0];
    const int*   ei  = (const int*)d_in[1];
    const float* ea  = (const float*)d_in[2];
    const float* w1r = (const float*)d_in[3];
    const float* w1n = (const float*)d_in[4];
    const float* b1  = (const float*)d_in[5];
    const float* w2r = (const float*)d_in[6];
    const float* w2n = (const float*)d_in[7];
    const float* b2  = (const float*)d_in[8];
    const float* we1 = (const float*)d_in[9];
    const float* be1 = (const float*)d_in[10];
    const float* we2 = (const float*)d_in[11];
    const float* be2 = (const float*)d_in[12];
    const float* we3 = (const float*)d_in[13];
    const float* be3 = (const float*)d_in[14];
    float* out = (float*)d_out;

    cudaFuncSetAttribute(k_npq, cudaFuncAttributeMaxDynamicSharedMemorySize,
                         SMN_TOTAL);
    cudaFuncSetAttribute(k_edge_mma, cudaFuncAttributeMaxDynamicSharedMemorySize,
                         SM_EDGE_TOTAL);

    k_zero<<<12500, 256>>>();
    k_agg1<<<N_EDGES / 256, 256>>>(x, ei);
    k_h1<<<N_NODES / 2, 256>>>(x, w1r, w1n, b1);
    k_agg2<<<N_EDGES / 8, 256>>>(ei);
    k_npq<<<NPQ_GRID, 256, SMN_TOTAL>>>(w2r, w2n, b2, we1);
    k_edge_mma<<<EDGE_GRID, 256, SM_EDGE_TOTAL>>>(ei, ea, we1, be1, we2, be2, we3, be3, out);
}

// round 11
// speedup vs baseline: 1.2239x; 1.2239x over previous
#include <cuda_runtime.h>
#include <cuda_bf16.h>
#include <cstdint>

#define N_NODES 100000
#define N_EDGES 1600000
#define HID 128

// ---------------- scratch (device globals; no allocation) ----------------
__device__ float g_cnt [N_NODES];
__device__ float g_agg1[N_NODES * 6];
__device__ float g_h1  [N_NODES * HID];
__device__ float g_agg2[N_NODES * HID];
__device__ float g_h2  [N_NODES * HID];
__device__ float g_p   [N_NODES * HID];   // h2 @ W_e1[0:128]
__device__ float g_q   [N_NODES * HID];   // h2 @ W_e1[128:256]

// ---------------- packed fp32x2 helpers ----------------
__device__ __forceinline__ void fma2(unsigned long long& acc,
                                     unsigned long long a, unsigned long long b) {
    asm("fma.rn.f32x2 %0, %1, %2, %0;" : "+l"(acc) : "l"(a), "l"(b));
}
__device__ __forceinline__ unsigned long long dup2(float x) {
    unsigned long long r;
    unsigned int u = __float_as_uint(x);
    asm("mov.b64 %0, {%1, %1};" : "=l"(r) : "r"(u));
    return r;
}
__device__ __forceinline__ float2 unpk2(unsigned long long v) {
    float2 f;
    asm("mov.b64 {%0, %1}, %2;" : "=f"(f.x), "=f"(f.y) : "l"(v));
    return f;
}

// ---------------- warp MMA helpers (baseline PTX) ----------------
__device__ __forceinline__ uint32_t smem_u32(const void* p) {
    uint32_t a;
    asm("{ .reg .u64 t; cvta.to.shared.u64 t, %1; cvt.u32.u64 %0, t; }" : "=r"(a) : "l"(p));
    return a;
}
__device__ __forceinline__ void mma_tf32(float* d, const uint32_t* a, const uint32_t* b) {
    asm volatile(
        "mma.sync.aligned.m16n8k8.row.col.f32.tf32.tf32.f32 "
        "{%0,%1,%2,%3}, {%4,%5,%6,%7}, {%8,%9}, {%0,%1,%2,%3};"
        : "+f"(d[0]), "+f"(d[1]), "+f"(d[2]), "+f"(d[3])
        : "r"(a[0]), "r"(a[1]), "r"(a[2]), "r"(a[3]), "r"(b[0]), "r"(b[1]));
}
__device__ __forceinline__ void ldsm4(uint32_t* r, uint32_t addr) {
    asm volatile("ldmatrix.sync.aligned.m8n8.x4.shared.b16 {%0,%1,%2,%3}, [%4];"
                 : "=r"(r[0]), "=r"(r[1]), "=r"(r[2]), "=r"(r[3]) : "r"(addr));
}
__device__ __forceinline__ uint32_t cvt_tf32(float x) {
    uint32_t u;
    asm("cvt.rna.tf32.f32 %0, %1;" : "=r"(u) : "f"(x));
    return u;
}

// ---------------- zero scratch accumulators ----------------
__global__ void k_zero() {
    int i = blockIdx.x * 256 + threadIdx.x;
    float4 z = make_float4(0.f, 0.f, 0.f, 0.f);
    if (i < N_NODES * HID / 4) reinterpret_cast<float4*>(g_agg2)[i] = z;
    if (i < N_NODES * 6 / 4)   reinterpret_cast<float4*>(g_agg1)[i] = z;
    if (i < N_NODES / 4)       reinterpret_cast<float4*>(g_cnt)[i]  = z;
}

// ---------------- SAGE layer 1 scatter ----------------
__global__ void k_agg1(const float* __restrict__ x, const int* __restrict__ ei) {
    int e = blockIdx.x * 256 + threadIdx.x;
    int s = ei[e];
    int d = ei[N_EDGES + e];
    atomicAdd(&g_cnt[d], 1.0f);
    const float2* xr = reinterpret_cast<const float2*>(x + s * 6);
    float* dst = &g_agg1[d * 6];
#pragma unroll
    for (int k = 0; k < 3; k++) {
        float2 v = xr[k];
        asm volatile("red.global.add.v2.f32 [%0], {%1, %2};"
                     :: "l"(dst + k * 2), "f"(v.x), "f"(v.y) : "memory");
    }
}

// ---------------- h1 = relu(x@W1r + mean1@W1n + b1) ----------------
__global__ void k_h1(const float* __restrict__ x,
                     const float* __restrict__ w1r, const float* __restrict__ w1n,
                     const float* __restrict__ b1) {
    int t = threadIdx.x;
    int node = blockIdx.x * 2 + (t >> 7);
    int j = t & 127;
    float inv = 1.0f / fmaxf(g_cnt[node], 1.0f);
    float acc = b1[j];
#pragma unroll
    for (int k = 0; k < 6; k++) {
        acc += x[node * 6 + k] * w1r[k * 128 + j]
             + g_agg1[node * 6 + k] * inv * w1n[k * 128 + j];
    }
    g_h1[node * 128 + j] = fmaxf(acc, 0.f);
}

// ---------------- scatter h1[src] into agg2 (vector red) ----------------
__global__ void k_agg2(const int* __restrict__ ei) {
    int w = blockIdx.x * 8 + (threadIdx.x >> 5);
    int lane = threadIdx.x & 31;
    int s = ei[w];
    int d = ei[N_EDGES + w];
    float4 v = *reinterpret_cast<const float4*>(&g_h1[s * 128 + lane * 4]);
    float* dst = &g_agg2[d * 128 + lane * 4];
    asm volatile("red.global.add.v4.f32 [%0], {%1, %2, %3, %4};"
                 :: "l"(dst), "f"(v.x), "f"(v.y), "f"(v.z), "f"(v.w) : "memory");
}

// ---------------- h2 = relu(h1@W2r + mean2@W2n + b2), dual-A GEMM ----------------
__global__ void k_h2(const float* __restrict__ W1, const float* __restrict__ W2,
                     const float* __restrict__ bias) {
    __shared__ __align__(16) float As1[16][64];
    __shared__ __align__(16) float As2[16][64];
    __shared__ __align__(16) float Bs1[16][64];
    __shared__ __align__(16) float Bs2[16][64];
    int t = threadIdx.x;
    int row0 = blockIdx.x * 64;
    int col0 = blockIdx.y * 64;
    int lnode = t >> 2;
    int lk4   = (t & 3) * 4;
    int lkB   = t >> 4;
    int ljB   = (t & 15) * 4;
    int tx = t & 15, ty = t >> 4;
    unsigned long long acc[4][2] = {};

    for (int k0 = 0; k0 < 128; k0 += 16) {
        int row = row0 + lnode;
        float4 a1, a2;
        if (row < N_NODES) {
            a1 = *reinterpret_cast<const float4*>(&g_h1[row * 128 + k0 + lk4]);
            a2 = *reinterpret_cast<const float4*>(&g_agg2[row * 128 + k0 + lk4]);
            float inv = 1.0f / fmaxf(g_cnt[row], 1.0f);
            a2.x *= inv; a2.y *= inv; a2.z *= inv; a2.w *= inv;
        } else {
            a1 = a2 = make_float4(0.f, 0.f, 0.f, 0.f);
        }
        As1[lk4 + 0][lnode] = a1.x; As1[lk4 + 1][lnode] = a1.y;
        As1[lk4 + 2][lnode] = a1.z; As1[lk4 + 3][lnode] = a1.w;
        As2[lk4 + 0][lnode] = a2.x; As2[lk4 + 1][lnode] = a2.y;
        As2[lk4 + 2][lnode] = a2.z; As2[lk4 + 3][lnode] = a2.w;
        *reinterpret_cast<float4*>(&Bs1[lkB][ljB]) =
            *reinterpret_cast<const float4*>(&W1[(k0 + lkB) * 128 + col0 + ljB]);
        *reinterpret_cast<float4*>(&Bs2[lkB][ljB]) =
            *reinterpret_cast<const float4*>(&W2[(k0 + lkB) * 128 + col0 + ljB]);
        __syncthreads();
#pragma unroll
        for (int kk = 0; kk < 16; kk++) {
            float4 a1v = *reinterpret_cast<float4*>(&As1[kk][ty * 4]);
            float4 a2v = *reinterpret_cast<float4*>(&As2[kk][ty * 4]);
            ulonglong2 b1v = *reinterpret_cast<ulonglong2*>(&Bs1[kk][tx * 4]);
            ulonglong2 b2v = *reinterpret_cast<ulonglong2*>(&Bs2[kk][tx * 4]);
            unsigned long long a1d[4] = {dup2(a1v.x), dup2(a1v.y), dup2(a1v.z), dup2(a1v.w)};
            unsigned long long a2d[4] = {dup2(a2v.x), dup2(a2v.y), dup2(a2v.z), dup2(a2v.w)};
#pragma unroll
            for (int i = 0; i < 4; i++) {
                fma2(acc[i][0], a1d[i], b1v.x);
                fma2(acc[i][0], a2d[i], b2v.x);
                fma2(acc[i][1], a1d[i], b1v.y);
                fma2(acc[i][1], a2d[i], b2v.y);
            }
        }
        __syncthreads();
    }

    int row = row0 + ty * 4;
    int col = col0 + tx * 4;
#pragma unroll
    for (int i = 0; i < 4; i++) {
        if (row + i < N_NODES) {
            float2 lo = unpk2(acc[i][0]);
            float2 hi = unpk2(acc[i][1]);
            float4 c;
            c.x = fmaxf(lo.x + bias[col + 0], 0.f);
            c.y = fmaxf(lo.y + bias[col + 1], 0.f);
            c.z = fmaxf(hi.x + bias[col + 2], 0.f);
            c.w = fmaxf(hi.y + bias[col + 3], 0.f);
            *reinterpret_cast<float4*>(&g_h2[(row + i) * 128 + col]) = c;
        }
    }
}

// ---------------- p = h2@W_a, q = h2@W_b ----------------
__global__ void k_pq(const float* __restrict__ we1) {
    __shared__ __align__(16) float As[16][64];
    __shared__ __align__(16) float Bs1[16][64];
    __shared__ __align__(16) float Bs2[16][64];
    int t = threadIdx.x;
    int row0 = blockIdx.x * 64;
    int col0 = blockIdx.y * 64;
    int lnode = t >> 2;
    int lk4   = (t & 3) * 4;
    int lkB   = t >> 4;
    int ljB   = (t & 15) * 4;
    int tx = t & 15, ty = t >> 4;
    unsigned long long acc1[4][2] = {};
    unsigned long long acc2[4][2] = {};

    for (int k0 = 0; k0 < 128; k0 += 16) {
        int row = row0 + lnode;
        float4 a;
        if (row < N_NODES)
            a = *reinterpret_cast<const float4*>(&g_h2[row * 128 + k0 + lk4]);
        else
            a = make_float4(0.f, 0.f, 0.f, 0.f);
        As[lk4 + 0][lnode] = a.x; As[lk4 + 1][lnode] = a.y;
        As[lk4 + 2][lnode] = a.z; As[lk4 + 3][lnode] = a.w;
        *reinterpret_cast<float4*>(&Bs1[lkB][ljB]) =
            *reinterpret_cast<const float4*>(&we1[(k0 + lkB) * 128 + col0 + ljB]);
        *reinterpret_cast<float4*>(&Bs2[lkB][ljB]) =
            *reinterpret_cast<const float4*>(&we1[(128 + k0 + lkB) * 128 + col0 + ljB]);
        __syncthreads();
#pragma unroll
        for (int kk = 0; kk < 16; kk++) {
            float4 av  = *reinterpret_cast<float4*>(&As[kk][ty * 4]);
            ulonglong2 b1v = *reinterpret_cast<ulonglong2*>(&Bs1[kk][tx * 4]);
            ulonglong2 b2v = *reinterpret_cast<ulonglong2*>(&Bs2[kk][tx * 4]);
            unsigned long long ad[4] = {dup2(av.x), dup2(av.y), dup2(av.z), dup2(av.w)};
#pragma unroll
            for (int i = 0; i < 4; i++) {
                fma2(acc1[i][0], ad[i], b1v.x);
                fma2(acc1[i][1], ad[i], b1v.y);
                fma2(acc2[i][0], ad[i], b2v.x);
                fma2(acc2[i][1], ad[i], b2v.y);
            }
        }
        __syncthreads();
    }

    int row = row0 + ty * 4;
    int col = col0 + tx * 4;
#pragma unroll
    for (int i = 0; i < 4; i++) {
        if (row + i < N_NODES) {
            float2 p0 = unpk2(acc1[i][0]), p1 = unpk2(acc1[i][1]);
            float2 q0 = unpk2(acc2[i][0]), q1 = unpk2(acc2[i][1]);
            *reinterpret_cast<float4*>(&g_p[(row + i) * 128 + col]) =
                make_float4(p0.x, p0.y, p1.x, p1.y);
            *reinterpret_cast<float4*>(&g_q[(row + i) * 128 + col]) =
                make_float4(q0.x, q0.y, q1.x, q1.y);
        }
    }
}

// ================= edge MLP via tf32 mma (single pass) ========================
// e1 = relu(p[src]+q[dst]+ea@Wc+b1) -> cvt.rna.tf32 -> smem A [128][132] fp32
// W2T [64][132] fp32(tf32) staged once. D = A@W2 via mma.m16n8k8.tf32,
// fragments loaded with the ldmatrix-b16-pair trick. fp32 accum.
// Epilogue: out = sum_c relu(D+b2)*w3 + b3. 2 CTAs/SM, double-buffered staging.
#define ARF 132                       // padded row floats (528 B)
#define SM_A      0                   // 128*528 = 67584
#define SM_B      67584               // 64*528  = 33792
#define SM_PA     101376              // float[128]
#define SM_PB     101888              // float[128]
#define SM_B2S    102400              // float[64]
#define SM_W3S    102656              // float[64]
#define SM_SRC    102912              // int[2][128]
#define SM_DST    103936              // int[2][128]
#define SM_EAS    104960              // float[2][512]
#define SM_EDGE_TOTAL 109056

#define N_TILES (N_EDGES / 128)
#define EDGE_GRID 296

__global__ __launch_bounds__(256, 2)
void k_edge_tf32(const int* __restrict__ ei, const float* __restrict__ ea,
                 const float* __restrict__ we1, const float* __restrict__ be1,
                 const float* __restrict__ we2, const float* __restrict__ be2,
                 const float* __restrict__ we3, const float* __restrict__ be3,
                 float* __restrict__ out) {
    extern __shared__ __align__(16) char smem[];
    uint32_t smem_base = smem_u32(smem);
    int t = threadIdx.x;
    int wid = t >> 5, lane = t & 31;
    int wm = wid >> 1;            // warp M tile: rows wm*32..+31
    int wn = wid & 1;             // warp N half: cols wn*32..+31

    float* pa  = (float*)(smem + SM_PA);
    float* pb  = (float*)(smem + SM_PB);
    float* b2s = (float*)(smem + SM_B2S);
    float* w3s = (float*)(smem + SM_W3S);
    int*   srcs = (int*)(smem + SM_SRC);     // [2][128]
    int*   dsts = (int*)(smem + SM_DST);     // [2][128]
    float* eas  = (float*)(smem + SM_EAS);   // [2][512]

    if (t < 64) { b2s[t] = be2[t]; w3s[t] = we3[t]; }

    // ---- per-thread MLP constants (k fixed per lane) ----
    int kq = lane * 4;
    float4 b1v = *reinterpret_cast<const float4*>(&be1[kq]);
    float4 wc0 = *reinterpret_cast<const float4*>(&we1[256 * 128 + kq]);
    float4 wc1 = *reinterpret_cast<const float4*>(&we1[257 * 128 + kq]);
    float4 wc2 = *reinterpret_cast<const float4*>(&we1[258 * 128 + kq]);
    float4 wc3 = *reinterpret_cast<const float4*>(&we1[259 * 128 + kq]);

    // ---- stage W2T (tf32) into smem: BT[n][k] = we2[k*64+n] ----
    for (int idx = t; idx < 64 * 128; idx += 256) {
        int n = idx >> 7, k = idx & 127;
        uint32_t w = cvt_tf32(we2[k * 64 + n]);
        *(uint32_t*)(smem + SM_B + (uint32_t)n * 528 + (uint32_t)k * 4) = w;
    }
    float be3v = be3[0];

    // ldmatrix per-lane source coords (byte offsets within tile rows)
    int arow = lane & 15;                         // A row within 16-row tile pair
    uint32_t acolb = (lane & 16) ? 16u : 0u;      // A col half (4 floats = 16B)
    int b_nrow = wn * 32 + ((lane >> 4) << 3) + (lane & 7);
    uint32_t b_kb = ((lane >> 3) & 1) ? 16u : 0u; // B k half (16B)
    uint32_t b_base = (uint32_t)b_nrow * 528 + b_kb;

    // ---- prologue: stage tile 0 into buffer 0 ----
    int tile = blockIdx.x;
    {
        int e0 = tile * 128;
        if (t < 128) srcs[t] = ei[e0 + t];
        else         dsts[t - 128] = ei[N_EDGES + e0 + (t - 128)];
        for (int i = t; i < 512; i += 256) eas[i] = ea[e0 * 4 + i];
    }
    __syncthreads();

    int buf = 0;
    for (; tile < N_TILES; tile += EDGE_GRID) {
        int e0 = tile * 128;
        int* sb = srcs + buf * 128;
        int* db = dsts + buf * 128;
        float* eb = eas + buf * 512;

        // ---- gather (float4, warp-per-edge) + e1 + cvt.tf32 into smem A ----
#pragma unroll 4
        for (int i = 0; i < 16; i++) {
            int edge = i * 8 + wid;
            int s = sb[edge], d = db[edge];
            float4 pv = *reinterpret_cast<const float4*>(&g_p[s * 128 + kq]);
            float4 qv = *reinterpret_cast<const float4*>(&g_q[d * 128 + kq]);
            float4 e4 = *reinterpret_cast<const float4*>(&eb[edge * 4]);
            float v[4];
            v[0] = pv.x + qv.x + b1v.x + e4.x * wc0.x + e4.y * wc1.x + e4.z * wc2.x + e4.w * wc3.x;
            v[1] = pv.y + qv.y + b1v.y + e4.x * wc0.y + e4.y * wc1.y + e4.z * wc2.y + e4.w * wc3.y;
            v[2] = pv.z + qv.z + b1v.z + e4.x * wc0.z + e4.y * wc1.z + e4.z * wc2.z + e4.w * wc3.z;
            v[3] = pv.w + qv.w + b1v.w + e4.x * wc0.w + e4.y * wc1.w + e4.z * wc2.w + e4.w * wc3.w;
            uint4 tv;
            tv.x = cvt_tf32(fmaxf(v[0], 0.f));
            tv.y = cvt_tf32(fmaxf(v[1], 0.f));
            tv.z = cvt_tf32(fmaxf(v[2], 0.f));
            tv.w = cvt_tf32(fmaxf(v[3], 0.f));
            *(uint4*)(smem + SM_A + (uint32_t)edge * 528 + (uint32_t)kq * 4) = tv;
        }

        // ---- stage next tile into other buffer (overlaps with gather) ----
        int nxt = tile + EDGE_GRID;
        if (nxt < N_TILES) {
            int e0n = nxt * 128;
            int* sn = srcs + (buf ^ 1) * 128;
            int* dn = dsts + (buf ^ 1) * 128;
            float* en = eas + (buf ^ 1) * 512;
            if (t < 128) sn[t] = ei[e0n + t];
            else         dn[t - 128] = ei[N_EDGES + e0n + (t - 128)];
            for (int i = t; i < 512; i += 256) en[i] = ea[e0n * 4 + i];
        }
        __syncthreads();

        // ---- tf32 MMA mainloop: warp tile 32(M)x32(N), K=128, k8 steps ----
        float acc[2][4][4];
#pragma unroll
        for (int mi = 0; mi < 2; mi++)
#pragma unroll
            for (int nn = 0; nn < 4; nn++)
#pragma unroll
                for (int r = 0; r < 4; r++) acc[mi][nn][r] = 0.f;

#pragma unroll
        for (int kk = 0; kk < 16; kk++) {
            uint32_t a0[4], a1[4];
            uint32_t aoff = (uint32_t)(wm * 32 + arow) * 528 + acolb + (uint32_t)kk * 32;
            ldsm4(a0, smem_base + SM_A + aoff);
            ldsm4(a1, smem_base + SM_A + aoff + 16 * 528);

            uint32_t b01[4], b23[4];
            uint32_t boff = b_base + (uint32_t)kk * 32;
            ldsm4(b01, smem_base + SM_B + boff);
            ldsm4(b23, smem_base + SM_B + boff + 16 * 528);
            uint32_t* bf[4] = {b01, b01 + 2, b23, b23 + 2};

#pragma unroll
            for (int nn = 0; nn < 4; nn++) {
                mma_tf32(acc[0][nn], a0, bf[nn]);
                mma_tf32(acc[1][nn], a1, bf[nn]);
            }
        }

        // ---- epilogue: relu(D+b2)*w3, reduce over N (atomic-free) ----
        float part[2][2] = {{0.f, 0.f}, {0.f, 0.f}};
#pragma unroll
        for (int mi = 0; mi < 2; mi++) {
#pragma unroll
            for (int nn = 0; nn < 4; nn++) {
                int c0 = wn * 32 + nn * 8 + (lane & 3) * 2;
                float w30 = w3s[c0], w31 = w3s[c0 + 1];
                float bb0 = b2s[c0], bb1 = b2s[c0 + 1];
                part[mi][0] += fmaxf(acc[mi][nn][0] + bb0, 0.f) * w30
                             + fmaxf(acc[mi][nn][1] + bb1, 0.f) * w31;
                part[mi][1] += fmaxf(acc[mi][nn][2] + bb0, 0.f) * w30
                             + fmaxf(acc[mi][nn][3] + bb1, 0.f) * w31;
            }
        }
#pragma unroll
        for (int mi = 0; mi < 2; mi++) {
#pragma unroll
            for (int g = 0; g < 2; g++) {
                part[mi][g] += __shfl_xor_sync(0xffffffffu, part[mi][g], 1);
                part[mi][g] += __shfl_xor_sync(0xffffffffu, part[mi][g], 2);
            }
        }
        if ((lane & 3) == 0) {
            float* pw = wn ? pb : pa;
            int r0 = wm * 32 + (lane >> 2);
            pw[r0]      = part[0][0];
            pw[r0 + 8]  = part[0][1];
            pw[r0 + 16] = part[1][0];
            pw[r0 + 24] = part[1][1];
        }
        __syncthreads();
        if (t < 128) out[e0 + t] = pa[t] + pb[t] + be3v;
        buf ^= 1;
    }
}

// ---------------- launch ----------------
extern "C" void kernel_launch(void* const* d_in, const int* in_sizes, int n_in,
                              void* d_out, int out_size) {
    const float* x   = (const float*)d_in[0];
    const int*   ei  = (const int*)d_in[1];
    const float* ea  = (const float*)d_in[2];
    const float* w1r = (const float*)d_in[3];
    const float* w1n = (const float*)d_in[4];
    const float* b1  = (const float*)d_in[5];
    const float* w2r = (const float*)d_in[6];
    const float* w2n = (const float*)d_in[7];
    const float* b2  = (const float*)d_in[8];
    const float* we1 = (const float*)d_in[9];
    const float* be1 = (const float*)d_in[10];
    const float* we2 = (const float*)d_in[11];
    const float* be2 = (const float*)d_in[12];
    const float* we3 = (const float*)d_in[13];
    const float* be3 = (const float*)d_in[14];
    float* out = (float*)d_out;

    cudaFuncSetAttribute(k_edge_tf32, cudaFuncAttributeMaxDynamicSharedMemorySize,
                         SM_EDGE_TOTAL);

    k_zero<<<12500, 256>>>();
    k_agg1<<<N_EDGES / 256, 256>>>(x, ei);
    k_h1<<<N_NODES / 2, 256>>>(x, w1r, w1n, b1);
    k_agg2<<<N_EDGES / 8, 256>>>(ei);
    k_h2<<<dim3((N_NODES + 63) / 64, 2), 256>>>(w2r, w2n, b2);
    k_pq<<<dim3((N_NODES + 63) / 64, 2), 256>>>(we1);
    k_edge_tf32<<<EDGE_GRID, 256, SM_EDGE_TOTAL>>>(ei, ea, we1, be1, we2, be2, we3, be3, out);
}

// round 12
// speedup vs baseline: 1.3601x; 1.1113x over previous
#include <cuda_runtime.h>
#include <cuda_bf16.h>
#include <cstdint>

#define N_NODES 100000
#define N_EDGES 1600000
#define HID 128

// ---------------- scratch (device globals; no allocation) ----------------
__device__ float g_cnt [N_NODES];
__device__ float g_agg1[N_NODES * 6];
__device__ float g_h1  [N_NODES * HID];
__device__ float g_agg2[N_NODES * HID];
__device__ float g_h2  [N_NODES * HID];
__device__ float g_p   [N_NODES * HID];   // h2 @ W_e1[0:128]
__device__ float g_q   [N_NODES * HID];   // h2 @ W_e1[128:256]

// ---------------- warp MMA helpers (baseline PTX) ----------------
__device__ __forceinline__ uint32_t smem_u32(const void* p) {
    uint32_t a;
    asm("{ .reg .u64 t; cvta.to.shared.u64 t, %1; cvt.u32.u64 %0, t; }" : "=r"(a) : "l"(p));
    return a;
}
__device__ __forceinline__ void mma_tf32(float* d, const uint32_t* a, const uint32_t* b) {
    asm volatile(
        "mma.sync.aligned.m16n8k8.row.col.f32.tf32.tf32.f32 "
        "{%0,%1,%2,%3}, {%4,%5,%6,%7}, {%8,%9}, {%0,%1,%2,%3};"
        : "+f"(d[0]), "+f"(d[1]), "+f"(d[2]), "+f"(d[3])
        : "r"(a[0]), "r"(a[1]), "r"(a[2]), "r"(a[3]), "r"(b[0]), "r"(b[1]));
}
__device__ __forceinline__ void ldsm4(uint32_t* r, uint32_t addr) {
    asm volatile("ldmatrix.sync.aligned.m8n8.x4.shared.b16 {%0,%1,%2,%3}, [%4];"
                 : "=r"(r[0]), "=r"(r[1]), "=r"(r[2]), "=r"(r[3]) : "r"(addr));
}
__device__ __forceinline__ uint32_t cvt_tf32(float x) {
    uint32_t u;
    asm("cvt.rna.tf32.f32 %0, %1;" : "=r"(u) : "f"(x));
    return u;
}

// ---------------- zero scratch accumulators ----------------
__global__ void k_zero() {
    int i = blockIdx.x * 256 + threadIdx.x;
    float4 z = make_float4(0.f, 0.f, 0.f, 0.f);
    if (i < N_NODES * HID / 4) reinterpret_cast<float4*>(g_agg2)[i] = z;
    if (i < N_NODES * 6 / 4)   reinterpret_cast<float4*>(g_agg1)[i] = z;
    if (i < N_NODES / 4)       reinterpret_cast<float4*>(g_cnt)[i]  = z;
}

// ---------------- SAGE layer 1 scatter ----------------
__global__ void k_agg1(const float* __restrict__ x, const int* __restrict__ ei) {
    int e = blockIdx.x * 256 + threadIdx.x;
    int s = ei[e];
    int d = ei[N_EDGES + e];
    atomicAdd(&g_cnt[d], 1.0f);
    const float2* xr = reinterpret_cast<const float2*>(x + s * 6);
    float* dst = &g_agg1[d * 6];
#pragma unroll
    for (int k = 0; k < 3; k++) {
        float2 v = xr[k];
        asm volatile("red.global.add.v2.f32 [%0], {%1, %2};"
                     :: "l"(dst + k * 2), "f"(v.x), "f"(v.y) : "memory");
    }
}

// ---------------- h1 = relu(x@W1r + mean1@W1n + b1) ----------------
__global__ void k_h1(const float* __restrict__ x,
                     const float* __restrict__ w1r, const float* __restrict__ w1n,
                     const float* __restrict__ b1) {
    int t = threadIdx.x;
    int node = blockIdx.x * 2 + (t >> 7);
    int j = t & 127;
    float inv = 1.0f / fmaxf(g_cnt[node], 1.0f);
    float acc = b1[j];
#pragma unroll
    for (int k = 0; k < 6; k++) {
        acc += x[node * 6 + k] * w1r[k * 128 + j]
             + g_agg1[node * 6 + k] * inv * w1n[k * 128 + j];
    }
    g_h1[node * 128 + j] = fmaxf(acc, 0.f);
}

// ---------------- scatter h1[src] into agg2 (vector red) ----------------
__global__ void k_agg2(const int* __restrict__ ei) {
    int w = blockIdx.x * 8 + (threadIdx.x >> 5);
    int lane = threadIdx.x & 31;
    int s = ei[w];
    int d = ei[N_EDGES + w];
    float4 v = *reinterpret_cast<const float4*>(&g_h1[s * 128 + lane * 4]);
    float* dst = &g_agg2[d * 128 + lane * 4];
    asm volatile("red.global.add.v4.f32 [%0], {%1, %2, %3, %4};"
                 :: "l"(dst), "f"(v.x), "f"(v.y), "f"(v.z), "f"(v.w) : "memory");
}

// ================= k_h2_tf32: h2 = relu([h1|mean]@[W2r;W2n]+b2) ===============
// Grid (M-tiles, 2 N-halves). B^T [64 n][256 k] fp32 staged ONCE per CTA;
// A chunks [64 rows][32 k] staged per k-chunk (144 B padded rows, ldsm-clean).
// Warp tile 16(M)x32(N) via mma.m16n8k8.tf32 with the ldsm-b16-pair trick.
#define H2_AS 0                       // 64*144   = 9216
#define H2_BS 9216                    // 64*1040  = 66560
#define H2_TOTAL 75776

__global__ __launch_bounds__(256, 2)
void k_h2_tf32(const float* __restrict__ w2r, const float* __restrict__ w2n,
               const float* __restrict__ b2) {
    extern __shared__ __align__(16) char smem[];
    uint32_t smem_base = smem_u32(smem);
    int t = threadIdx.x, wid = t >> 5, lane = t & 31;
    int wm = wid >> 1;                 // rows wm*16..+15
    int wn = wid & 1;                  // cols wn*32..+31
    int row0 = blockIdx.x * 64;
    int nbase = blockIdx.y * 64;

    // ---- stage B once: BT[n][k] = (k<128 ? w2r[k][nb+n] : w2n[k-128][nb+n]) ----
#pragma unroll 8
    for (int i = 0; i < 64; i++) {
        int idx = i * 256 + t;
        int k = idx >> 6, n = idx & 63;
        float w = (k < 128) ? w2r[k * 128 + nbase + n]
                            : w2n[(k - 128) * 128 + nbase + n];
        *(uint32_t*)(smem + H2_BS + (uint32_t)n * 1040 + (uint32_t)k * 4) = cvt_tf32(w);
    }

    // per-thread A staging coords
    int arow_st = t >> 2;
    int akg = (t & 3) * 8;
    int grow_st = row0 + arow_st;
    bool valid = grow_st < N_NODES;
    float inv = valid ? (1.0f / fmaxf(g_cnt[grow_st], 1.0f)) : 0.f;

    // ldsm coords (same mapping as validated k_edge_tf32)
    int arow = lane & 15;
    uint32_t acolb = (lane & 16) ? 16u : 0u;
    int b_nrow = ((lane >> 4) << 3) + (lane & 7);       // 0..15 (per 16-row group)
    uint32_t b_kb = ((lane >> 3) & 1) ? 16u : 0u;

    float acc[4][4] = {};

#pragma unroll 1
    for (int kc = 0; kc < 8; kc++) {
        // ---- stage A chunk [64][32] ----
        {
            float v[8] = {0, 0, 0, 0, 0, 0, 0, 0};
            if (valid) {
                const float* src = (kc < 4)
                    ? &g_h1[(size_t)grow_st * 128 + kc * 32 + akg]
                    : &g_agg2[(size_t)grow_st * 128 + (kc - 4) * 32 + akg];
                float4 v0 = *reinterpret_cast<const float4*>(src);
                float4 v1 = *reinterpret_cast<const float4*>(src + 4);
                float sc = (kc < 4) ? 1.f : inv;
                v[0] = v0.x * sc; v[1] = v0.y * sc; v[2] = v0.z * sc; v[3] = v0.w * sc;
                v[4] = v1.x * sc; v[5] = v1.y * sc; v[6] = v1.z * sc; v[7] = v1.w * sc;
            }
            uint4 t0, t1;
            t0.x = cvt_tf32(v[0]); t0.y = cvt_tf32(v[1]);
            t0.z = cvt_tf32(v[2]); t0.w = cvt_tf32(v[3]);
            t1.x = cvt_tf32(v[4]); t1.y = cvt_tf32(v[5]);
            t1.z = cvt_tf32(v[6]); t1.w = cvt_tf32(v[7]);
            char* dst = smem + H2_AS + (uint32_t)arow_st * 144 + (uint32_t)akg * 4;
            *(uint4*)(dst) = t0;
            *(uint4*)(dst + 16) = t1;
        }
        __syncthreads();

        // ---- mma: 4 k8-steps ----
#pragma unroll
        for (int ks = 0; ks < 4; ks++) {
            uint32_t a[4];
            ldsm4(a, smem_base + H2_AS + (uint32_t)(wm * 16 + arow) * 144
                     + acolb + (uint32_t)ks * 32);
            uint32_t b01[4], b23[4];
            uint32_t boff = (uint32_t)(wn * 32 + b_nrow) * 1040 + b_kb
                          + (uint32_t)(kc * 32 + ks * 8) * 4;
            ldsm4(b01, smem_base + H2_BS + boff);
            ldsm4(b23, smem_base + H2_BS + boff + 16 * 1040);
            uint32_t* bf[4] = {b01, b01 + 2, b23, b23 + 2};
#pragma unroll
            for (int nn = 0; nn < 4; nn++) mma_tf32(acc[nn], a, bf[nn]);
        }
        __syncthreads();
    }

    // ---- epilogue: relu(acc + b2) -> g_h2 ----
    int erow = row0 + wm * 16 + (lane >> 2);
    int ecol = nbase + wn * 32 + (lane & 3) * 2;
#pragma unroll
    for (int nn = 0; nn < 4; nn++) {
        int c = ecol + nn * 8;
        float b0 = b2[c], b1 = b2[c + 1];
        if (erow < N_NODES) {
            float2 o = make_float2(fmaxf(acc[nn][0] + b0, 0.f),
                                   fmaxf(acc[nn][1] + b1, 0.f));
            *reinterpret_cast<float2*>(&g_h2[(size_t)erow * 128 + c]) = o;
        }
        if (erow + 8 < N_NODES) {
            float2 o = make_float2(fmaxf(acc[nn][2] + b0, 0.f),
                                   fmaxf(acc[nn][3] + b1, 0.f));
            *reinterpret_cast<float2*>(&g_h2[(size_t)(erow + 8) * 128 + c]) = o;
        }
    }
}

// ================= k_pq_tf32: p = h2@Wa, q = h2@Wb ============================
// Grid (M-tiles, 4 N-quarters of [Wa|Wb]). Same skeleton as k_h2_tf32, K=128.
#define PQ_AS 0                       // 64*144  = 9216
#define PQ_BS 9216                    // 64*528  = 33792
#define PQ_TOTAL 43008

__global__ __launch_bounds__(256, 2)
void k_pq_tf32(const float* __restrict__ we1) {
    extern __shared__ __align__(16) char smem[];
    uint32_t smem_base = smem_u32(smem);
    int t = threadIdx.x, wid = t >> 5, lane = t & 31;
    int wm = wid >> 1;
    int wn = wid & 1;
    int row0 = blockIdx.x * 64;
    int qtr = blockIdx.y;              // 0,1 -> p cols 0/64 ; 2,3 -> q cols 0/64
    int nbase = (qtr & 1) * 64;
    int krow0 = (qtr < 2) ? 0 : 128;   // Wb rows start at 128 in we1

    // ---- stage B once: BT[n][k] = we1[(krow0+k)*128 + nbase + n] ----
#pragma unroll 8
    for (int i = 0; i < 32; i++) {
        int idx = i * 256 + t;
        int k = idx >> 6, n = idx & 63;
        float w = we1[(krow0 + k) * 128 + nbase + n];
        *(uint32_t*)(smem + PQ_BS + (uint32_t)n * 528 + (uint32_t)k * 4) = cvt_tf32(w);
    }

    int arow_st = t >> 2;
    int akg = (t & 3) * 8;
    int grow_st = row0 + arow_st;
    bool valid = grow_st < N_NODES;

    int arow = lane & 15;
    uint32_t acolb = (lane & 16) ? 16u : 0u;
    int b_nrow = ((lane >> 4) << 3) + (lane & 7);
    uint32_t b_kb = ((lane >> 3) & 1) ? 16u : 0u;

    float acc[4][4] = {};

#pragma unroll 1
    for (int kc = 0; kc < 4; kc++) {
        {
            float v[8] = {0, 0, 0, 0, 0, 0, 0, 0};
            if (valid) {
                const float* src = &g_h2[(size_t)grow_st * 128 + kc * 32 + akg];
                float4 v0 = *reinterpret_cast<const float4*>(src);
                float4 v1 = *reinterpret_cast<const float4*>(src + 4);
                v[0] = v0.x; v[1] = v0.y; v[2] = v0.z; v[3] = v0.w;
                v[4] = v1.x; v[5] = v1.y; v[6] = v1.z; v[7] = v1.w;
            }
            uint4 t0, t1;
            t0.x = cvt_tf32(v[0]); t0.y = cvt_tf32(v[1]);
            t0.z = cvt_tf32(v[2]); t0.w = cvt_tf32(v[3]);
            t1.x = cvt_tf32(v[4]); t1.y = cvt_tf32(v[5]);
            t1.z = cvt_tf32(v[6]); t1.w = cvt_tf32(v[7]);
            char* dst = smem + PQ_AS + (uint32_t)arow_st * 144 + (uint32_t)akg * 4;
            *(uint4*)(dst) = t0;
            *(uint4*)(dst + 16) = t1;
        }
        __syncthreads();

#pragma unroll
        for (int ks = 0; ks < 4; ks++) {
            uint32_t a[4];
            ldsm4(a, smem_base + PQ_AS + (uint32_t)(wm * 16 + arow) * 144
                     + acolb + (uint32_t)ks * 32);
            uint32_t b01[4], b23[4];
            uint32_t boff = (uint32_t)(wn * 32 + b_nrow) * 528 + b_kb
                          + (uint32_t)(kc * 32 + ks * 8) * 4;
            ldsm4(b01, smem_base + PQ_BS + boff);
            ldsm4(b23, smem_base + PQ_BS + boff + 16 * 528);
            uint32_t* bf[4] = {b01, b01 + 2, b23, b23 + 2};
#pragma unroll
            for (int nn = 0; nn < 4; nn++) mma_tf32(acc[nn], a, bf[nn]);
        }
        __syncthreads();
    }

    float* dstg = (qtr < 2) ? g_p : g_q;
    int erow = row0 + wm * 16 + (lane >> 2);
    int ecol = nbase + wn * 32 + (lane & 3) * 2;
#pragma unroll
    for (int nn = 0; nn < 4; nn++) {
        int c = ecol + nn * 8;
        if (erow < N_NODES)
            *reinterpret_cast<float2*>(&dstg[(size_t)erow * 128 + c]) =
                make_float2(acc[nn][0], acc[nn][1]);
        if (erow + 8 < N_NODES)
            *reinterpret_cast<float2*>(&dstg[(size_t)(erow + 8) * 128 + c]) =
                make_float2(acc[nn][2], acc[nn][3]);
    }
}

// ================= edge MLP via tf32 mma (unchanged from R10) =================
#define ARF 132
#define SM_A      0
#define SM_B      67584
#define SM_PA     101376
#define SM_PB     101888
#define SM_B2S    102400
#define SM_W3S    102656
#define SM_SRC    102912
#define SM_DST    103936
#define SM_EAS    104960
#define SM_EDGE_TOTAL 109056

#define N_TILES (N_EDGES / 128)
#define EDGE_GRID 296

__global__ __launch_bounds__(256, 2)
void k_edge_tf32(const int* __restrict__ ei, const float* __restrict__ ea,
                 const float* __restrict__ we1, const float* __restrict__ be1,
                 const float* __restrict__ we2, const float* __restrict__ be2,
                 const float* __restrict__ we3, const float* __restrict__ be3,
                 float* __restrict__ out) {
    extern __shared__ __align__(16) char smem[];
    uint32_t smem_base = smem_u32(smem);
    int t = threadIdx.x;
    int wid = t >> 5, lane = t & 31;
    int wm = wid >> 1;
    int wn = wid & 1;

    float* pa  = (float*)(smem + SM_PA);
    float* pb  = (float*)(smem + SM_PB);
    float* b2s = (float*)(smem + SM_B2S);
    float* w3s = (float*)(smem + SM_W3S);
    int*   srcs = (int*)(smem + SM_SRC);
    int*   dsts = (int*)(smem + SM_DST);
    float* eas  = (float*)(smem + SM_EAS);

    if (t < 64) { b2s[t] = be2[t]; w3s[t] = we3[t]; }

    int kq = lane * 4;
    float4 b1v = *reinterpret_cast<const float4*>(&be1[kq]);
    float4 wc0 = *reinterpret_cast<const float4*>(&we1[256 * 128 + kq]);
    float4 wc1 = *reinterpret_cast<const float4*>(&we1[257 * 128 + kq]);
    float4 wc2 = *reinterpret_cast<const float4*>(&we1[258 * 128 + kq]);
    float4 wc3 = *reinterpret_cast<const float4*>(&we1[259 * 128 + kq]);

    for (int idx = t; idx < 64 * 128; idx += 256) {
        int n = idx >> 7, k = idx & 127;
        uint32_t w = cvt_tf32(we2[k * 64 + n]);
        *(uint32_t*)(smem + SM_B + (uint32_t)n * 528 + (uint32_t)k * 4) = w;
    }
    float be3v = be3[0];

    int arow = lane & 15;
    uint32_t acolb = (lane & 16) ? 16u : 0u;
    int b_nrow = wn * 32 + ((lane >> 4) << 3) + (lane & 7);
    uint32_t b_kb = ((lane >> 3) & 1) ? 16u : 0u;
    uint32_t b_base = (uint32_t)b_nrow * 528 + b_kb;

    int tile = blockIdx.x;
    {
        int e0 = tile * 128;
        if (t < 128) srcs[t] = ei[e0 + t];
        else         dsts[t - 128] = ei[N_EDGES + e0 + (t - 128)];
        for (int i = t; i < 512; i += 256) eas[i] = ea[e0 * 4 + i];
    }
    __syncthreads();

    int buf = 0;
    for (; tile < N_TILES; tile += EDGE_GRID) {
        int e0 = tile * 128;
        int* sb = srcs + buf * 128;
        int* db = dsts + buf * 128;
        float* eb = eas + buf * 512;

#pragma unroll 4
        for (int i = 0; i < 16; i++) {
            int edge = i * 8 + wid;
            int s = sb[edge], d = db[edge];
            float4 pv = *reinterpret_cast<const float4*>(&g_p[s * 128 + kq]);
            float4 qv = *reinterpret_cast<const float4*>(&g_q[d * 128 + kq]);
            float4 e4 = *reinterpret_cast<const float4*>(&eb[edge * 4]);
            float v[4];
            v[0] = pv.x + qv.x + b1v.x + e4.x * wc0.x + e4.y * wc1.x + e4.z * wc2.x + e4.w * wc3.x;
            v[1] = pv.y + qv.y + b1v.y + e4.x * wc0.y + e4.y * wc1.y + e4.z * wc2.y + e4.w * wc3.y;
            v[2] = pv.z + qv.z + b1v.z + e4.x * wc0.z + e4.y * wc1.z + e4.z * wc2.z + e4.w * wc3.z;
            v[3] = pv.w + qv.w + b1v.w + e4.x * wc0.w + e4.y * wc1.w + e4.z * wc2.w + e4.w * wc3.w;
            uint4 tv;
            tv.x = cvt_tf32(fmaxf(v[0], 0.f));
            tv.y = cvt_tf32(fmaxf(v[1], 0.f));
            tv.z = cvt_tf32(fmaxf(v[2], 0.f));
            tv.w = cvt_tf32(fmaxf(v[3], 0.f));
            *(uint4*)(smem + SM_A + (uint32_t)edge * 528 + (uint32_t)kq * 4) = tv;
        }

        int nxt = tile + EDGE_GRID;
        if (nxt < N_TILES) {
            int e0n = nxt * 128;
            int* sn = srcs + (buf ^ 1) * 128;
            int* dn = dsts + (buf ^ 1) * 128;
            float* en = eas + (buf ^ 1) * 512;
            if (t < 128) sn[t] = ei[e0n + t];
            else         dn[t - 128] = ei[N_EDGES + e0n + (t - 128)];
            for (int i = t; i < 512; i += 256) en[i] = ea[e0n * 4 + i];
        }
        __syncthreads();

        float acc[2][4][4];
#pragma unroll
        for (int mi = 0; mi < 2; mi++)
#pragma unroll
            for (int nn = 0; nn < 4; nn++)
#pragma unroll
                for (int r = 0; r < 4; r++) acc[mi][nn][r] = 0.f;

#pragma unroll
        for (int kk = 0; kk < 16; kk++) {
            uint32_t a0[4], a1[4];
            uint32_t aoff = (uint32_t)(wm * 32 + arow) * 528 + acolb + (uint32_t)kk * 32;
            ldsm4(a0, smem_base + SM_A + aoff);
            ldsm4(a1, smem_base + SM_A + aoff + 16 * 528);

            uint32_t b01[4], b23[4];
            uint32_t boff = b_base + (uint32_t)kk * 32;
            ldsm4(b01, smem_base + SM_B + boff);
            ldsm4(b23, smem_base + SM_B + boff + 16 * 528);
            uint32_t* bf[4] = {b01, b01 + 2, b23, b23 + 2};

#pragma unroll
            for (int nn = 0; nn < 4; nn++) {
                mma_tf32(acc[0][nn], a0, bf[nn]);
                mma_tf32(acc[1][nn], a1, bf[nn]);
            }
        }

        float part[2][2] = {{0.f, 0.f}, {0.f, 0.f}};
#pragma unroll
        for (int mi = 0; mi < 2; mi++) {
#pragma unroll
            for (int nn = 0; nn < 4; nn++) {
                int c0 = wn * 32 + nn * 8 + (lane & 3) * 2;
                float w30 = w3s[c0], w31 = w3s[c0 + 1];
                float bb0 = b2s[c0], bb1 = b2s[c0 + 1];
                part[mi][0] += fmaxf(acc[mi][nn][0] + bb0, 0.f) * w30
                             + fmaxf(acc[mi][nn][1] + bb1, 0.f) * w31;
                part[mi][1] += fmaxf(acc[mi][nn][2] + bb0, 0.f) * w30
                             + fmaxf(acc[mi][nn][3] + bb1, 0.f) * w31;
            }
        }
#pragma unroll
        for (int mi = 0; mi < 2; mi++) {
#pragma unroll
            for (int g = 0; g < 2; g++) {
                part[mi][g] += __shfl_xor_sync(0xffffffffu, part[mi][g], 1);
                part[mi][g] += __shfl_xor_sync(0xffffffffu, part[mi][g], 2);
            }
        }
        if ((lane & 3) == 0) {
            float* pw = wn ? pb : pa;
            int r0 = wm * 32 + (lane >> 2);
            pw[r0]      = part[0][0];
            pw[r0 + 8]  = part[0][1];
            pw[r0 + 16] = part[1][0];
            pw[r0 + 24] = part[1][1];
        }
        __syncthreads();
        if (t < 128) out[e0 + t] = pa[t] + pb[t] + be3v;
        buf ^= 1;
    }
}

// ---------------- launch ----------------
extern "C" void kernel_launch(void* const* d_in, const int* in_sizes, int n_in,
                              void* d_out, int out_size) {
    const float* x   = (const float*)d_in[0];
    const int*   ei  = (const int*)d_in[1];
    const float* ea  = (const float*)d_in[2];
    const float* w1r = (const float*)d_in[3];
    const float* w1n = (const float*)d_in[4];
    const float* b1  = (const float*)d_in[5];
    const float* w2r = (const float*)d_in[6];
    const float* w2n = (const float*)d_in[7];
    const float* b2  = (const float*)d_in[8];
    const float* we1 = (const float*)d_in[9];
    const float* be1 = (const float*)d_in[10];
    const float* we2 = (const float*)d_in[11];
    const float* be2 = (const float*)d_in[12];
    const float* we3 = (const float*)d_in[13];
    const float* be3 = (const float*)d_in[14];
    float* out = (float*)d_out;

    cudaFuncSetAttribute(k_h2_tf32, cudaFuncAttributeMaxDynamicSharedMemorySize,
                         H2_TOTAL);
    cudaFuncSetAttribute(k_pq_tf32, cudaFuncAttributeMaxDynamicSharedMemorySize,
                         PQ_TOTAL);
    cudaFuncSetAttribute(k_edge_tf32, cudaFuncAttributeMaxDynamicSharedMemorySize,
                         SM_EDGE_TOTAL);

    k_zero<<<12500, 256>>>();
    k_agg1<<<N_EDGES / 256, 256>>>(x, ei);
    k_h1<<<N_NODES / 2, 256>>>(x, w1r, w1n, b1);
    k_agg2<<<N_EDGES / 8, 256>>>(ei);
    k_h2_tf32<<<dim3((N_NODES + 63) / 64, 2), 256, H2_TOTAL>>>(w2r, w2n, b2);
    k_pq_tf32<<<dim3((N_NODES + 63) / 64, 4), 256, PQ_TOTAL>>>(we1);
    k_edge_tf32<<<EDGE_GRID, 256, SM_EDGE_TOTAL>>>(ei, ea, we1, be1, we2, be2, we3, be3, out);
}

// round 13
// speedup vs baseline: 1.5604x; 1.1473x over previous
#include <cuda_runtime.h>
#include <cuda_bf16.h>
#include <cstdint>

#define N_NODES 100000
#define N_EDGES 1600000
#define HID 128
#define SCAN_B 98                    // ceil(100000/1024)

// ---------------- scratch (device globals; no allocation) ----------------
__device__ int   g_deg [N_NODES];
__device__ int   g_off [N_NODES];
__device__ int   g_cur [N_NODES];
__device__ int   g_bsum[128];
__device__ int   g_elist[N_EDGES];   // src ids grouped by dst
__device__ float g_h1  [N_NODES * HID];
__device__ float g_agg2[N_NODES * HID];   // mean of h1 over in-edges
__device__ float g_h2  [N_NODES * HID];
__device__ float g_p   [N_NODES * HID];
__device__ float g_q   [N_NODES * HID];

// ---------------- warp MMA helpers (baseline PTX) ----------------
__device__ __forceinline__ uint32_t smem_u32(const void* p) {
    uint32_t a;
    asm("{ .reg .u64 t; cvta.to.shared.u64 t, %1; cvt.u32.u64 %0, t; }" : "=r"(a) : "l"(p));
    return a;
}
__device__ __forceinline__ void mma_tf32(float* d, const uint32_t* a, const uint32_t* b) {
    asm volatile(
        "mma.sync.aligned.m16n8k8.row.col.f32.tf32.tf32.f32 "
        "{%0,%1,%2,%3}, {%4,%5,%6,%7}, {%8,%9}, {%0,%1,%2,%3};"
        : "+f"(d[0]), "+f"(d[1]), "+f"(d[2]), "+f"(d[3])
        : "r"(a[0]), "r"(a[1]), "r"(a[2]), "r"(a[3]), "r"(b[0]), "r"(b[1]));
}
__device__ __forceinline__ void ldsm4(uint32_t* r, uint32_t addr) {
    asm volatile("ldmatrix.sync.aligned.m8n8.x4.shared.b16 {%0,%1,%2,%3}, [%4];"
                 : "=r"(r[0]), "=r"(r[1]), "=r"(r[2]), "=r"(r[3]) : "r"(addr));
}
__device__ __forceinline__ uint32_t cvt_tf32(float x) {
    uint32_t u;
    asm("cvt.rna.tf32.f32 %0, %1;" : "=r"(u) : "f"(x));
    return u;
}

// ================== CSR build ==================
__global__ void k_zero_deg() {
    int i = blockIdx.x * 1024 + threadIdx.x;
    if (i < N_NODES) g_deg[i] = 0;
}
__global__ void k_hist(const int* __restrict__ ei) {
    int e = blockIdx.x * 256 + threadIdx.x;
    atomicAdd(&g_deg[ei[N_EDGES + e]], 1);
}
__global__ void k_scan1() {
    __shared__ int sh[1024];
    int tid = threadIdx.x;
    int i = blockIdx.x * 1024 + tid;
    int v = (i < N_NODES) ? g_deg[i] : 0;
    sh[tid] = v;
    __syncthreads();
#pragma unroll
    for (int ofs = 1; ofs < 1024; ofs <<= 1) {
        int o = (tid >= ofs) ? sh[tid - ofs] : 0;
        __syncthreads();
        sh[tid] += o;
        __syncthreads();
    }
    if (i < N_NODES) g_off[i] = sh[tid] - v;
    if (tid == 1023) g_bsum[blockIdx.x] = sh[1023];
}
__global__ void k_scan2() {
    __shared__ int sh[128];
    int t = threadIdx.x;
    int v = (t < SCAN_B) ? g_bsum[t] : 0;
    sh[t] = v;
    __syncthreads();
#pragma unroll
    for (int ofs = 1; ofs < 128; ofs <<= 1) {
        int o = (t >= ofs) ? sh[t - ofs] : 0;
        __syncthreads();
        sh[t] += o;
        __syncthreads();
    }
    if (t < SCAN_B) g_bsum[t] = sh[t] - v;
}
__global__ void k_scan3() {
    int i = blockIdx.x * 1024 + threadIdx.x;
    if (i < N_NODES) {
        int o = g_off[i] + g_bsum[blockIdx.x];
        g_off[i] = o;
        g_cur[i] = o;
    }
}
__global__ void k_scatter(const int* __restrict__ ei) {
    int e = blockIdx.x * 256 + threadIdx.x;
    int s = ei[e];
    int d = ei[N_EDGES + e];
    int pos = atomicAdd(&g_cur[d], 1);
    g_elist[pos] = s;
}

// ============ k_h1g: fused x-mean gather + h1 MLP (warp per node) ============
__global__ void k_h1g(const float* __restrict__ x,
                      const float* __restrict__ w1r, const float* __restrict__ w1n,
                      const float* __restrict__ b1) {
    int t = threadIdx.x;
    int lane = t & 31;
    int node = blockIdx.x * 8 + (t >> 5);

    // per-lane weights for cols lane*4..+3
    float4 wr[6], wn[6];
#pragma unroll
    for (int k = 0; k < 6; k++) {
        wr[k] = *reinterpret_cast<const float4*>(&w1r[k * 128 + lane * 4]);
        wn[k] = *reinterpret_cast<const float4*>(&w1n[k * 128 + lane * 4]);
    }
    float4 bv = *reinterpret_cast<const float4*>(&b1[lane * 4]);

    int deg = g_deg[node];
    int off = g_off[node];

    // gather sum of x[src] (6 dims) over in-edges
    float a0 = 0.f, a1 = 0.f, a2 = 0.f, a3 = 0.f, a4 = 0.f, a5 = 0.f;
    for (int i = lane; i < deg; i += 32) {
        int s = g_elist[off + i];
        const float2* xr = reinterpret_cast<const float2*>(x + s * 6);
        float2 v0 = xr[0], v1 = xr[1], v2 = xr[2];
        a0 += v0.x; a1 += v0.y; a2 += v1.x; a3 += v1.y; a4 += v2.x; a5 += v2.y;
    }
#pragma unroll
    for (int ofs = 16; ofs > 0; ofs >>= 1) {
        a0 += __shfl_xor_sync(0xffffffffu, a0, ofs);
        a1 += __shfl_xor_sync(0xffffffffu, a1, ofs);
        a2 += __shfl_xor_sync(0xffffffffu, a2, ofs);
        a3 += __shfl_xor_sync(0xffffffffu, a3, ofs);
        a4 += __shfl_xor_sync(0xffffffffu, a4, ofs);
        a5 += __shfl_xor_sync(0xffffffffu, a5, ofs);
    }
    float inv = 1.0f / fmaxf((float)deg, 1.0f);
    float m[6] = {a0 * inv, a1 * inv, a2 * inv, a3 * inv, a4 * inv, a5 * inv};

    const float2* xr = reinterpret_cast<const float2*>(x + node * 6);
    float2 x0 = xr[0], x1 = xr[1], x2 = xr[2];
    float xv[6] = {x0.x, x0.y, x1.x, x1.y, x2.x, x2.y};

    float4 h = bv;
#pragma unroll
    for (int k = 0; k < 6; k++) {
        h.x += xv[k] * wr[k].x + m[k] * wn[k].x;
        h.y += xv[k] * wr[k].y + m[k] * wn[k].y;
        h.z += xv[k] * wr[k].z + m[k] * wn[k].z;
        h.w += xv[k] * wr[k].w + m[k] * wn[k].w;
    }
    h.x = fmaxf(h.x, 0.f); h.y = fmaxf(h.y, 0.f);
    h.z = fmaxf(h.z, 0.f); h.w = fmaxf(h.w, 0.f);
    *reinterpret_cast<float4*>(&g_h1[(size_t)node * 128 + lane * 4]) = h;
}

// ============ k_gather2: mean of h1[srcs] -> g_agg2 (warp per node) ==========
__global__ void k_gather2() {
    int t = threadIdx.x;
    int lane = t & 31;
    int node = blockIdx.x * 8 + (t >> 5);
    int deg = g_deg[node];
    int off = g_off[node];

    float4 acc = make_float4(0.f, 0.f, 0.f, 0.f);
    int i = 0;
    for (; i + 4 <= deg; i += 4) {
        int s0 = g_elist[off + i + 0];
        int s1 = g_elist[off + i + 1];
        int s2 = g_elist[off + i + 2];
        int s3 = g_elist[off + i + 3];
        float4 v0 = *reinterpret_cast<const float4*>(&g_h1[(size_t)s0 * 128 + lane * 4]);
        float4 v1 = *reinterpret_cast<const float4*>(&g_h1[(size_t)s1 * 128 + lane * 4]);
        float4 v2 = *reinterpret_cast<const float4*>(&g_h1[(size_t)s2 * 128 + lane * 4]);
        float4 v3 = *reinterpret_cast<const float4*>(&g_h1[(size_t)s3 * 128 + lane * 4]);
        acc.x += v0.x + v1.x + v2.x + v3.x;
        acc.y += v0.y + v1.y + v2.y + v3.y;
        acc.z += v0.z + v1.z + v2.z + v3.z;
        acc.w += v0.w + v1.w + v2.w + v3.w;
    }
    for (; i < deg; i++) {
        int s = g_elist[off + i];
        float4 v = *reinterpret_cast<const float4*>(&g_h1[(size_t)s * 128 + lane * 4]);
        acc.x += v.x; acc.y += v.y; acc.z += v.z; acc.w += v.w;
    }
    float inv = 1.0f / fmaxf((float)deg, 1.0f);
    acc.x *= inv; acc.y *= inv; acc.z *= inv; acc.w *= inv;
    *reinterpret_cast<float4*>(&g_agg2[(size_t)node * 128 + lane * 4]) = acc;
}

// ================= k_h2_tf32: h2 = relu([h1|mean]@[W2r;W2n]+b2) ===============
#define H2_AS 0                       // 64*144   = 9216
#define H2_BS 9216                    // 64*1040  = 66560
#define H2_TOTAL 75776

__global__ __launch_bounds__(256, 2)
void k_h2_tf32(const float* __restrict__ w2r, const float* __restrict__ w2n,
               const float* __restrict__ b2) {
    extern __shared__ __align__(16) char smem[];
    uint32_t smem_base = smem_u32(smem);
    int t = threadIdx.x, wid = t >> 5, lane = t & 31;
    int wm = wid >> 1;
    int wn = wid & 1;
    int row0 = blockIdx.x * 64;
    int nbase = blockIdx.y * 64;

#pragma unroll 8
    for (int i = 0; i < 64; i++) {
        int idx = i * 256 + t;
        int k = idx >> 6, n = idx & 63;
        float w = (k < 128) ? w2r[k * 128 + nbase + n]
                            : w2n[(k - 128) * 128 + nbase + n];
        *(uint32_t*)(smem + H2_BS + (uint32_t)n * 1040 + (uint32_t)k * 4) = cvt_tf32(w);
    }

    int arow_st = t >> 2;
    int akg = (t & 3) * 8;
    int grow_st = row0 + arow_st;
    bool valid = grow_st < N_NODES;

    int arow = lane & 15;
    uint32_t acolb = (lane & 16) ? 16u : 0u;
    int b_nrow = ((lane >> 4) << 3) + (lane & 7);
    uint32_t b_kb = ((lane >> 3) & 1) ? 16u : 0u;

    float acc[4][4] = {};

#pragma unroll 1
    for (int kc = 0; kc < 8; kc++) {
        {
            float v[8] = {0, 0, 0, 0, 0, 0, 0, 0};
            if (valid) {
                const float* src = (kc < 4)
                    ? &g_h1[(size_t)grow_st * 128 + kc * 32 + akg]
                    : &g_agg2[(size_t)grow_st * 128 + (kc - 4) * 32 + akg];
                float4 v0 = *reinterpret_cast<const float4*>(src);
                float4 v1 = *reinterpret_cast<const float4*>(src + 4);
                v[0] = v0.x; v[1] = v0.y; v[2] = v0.z; v[3] = v0.w;
                v[4] = v1.x; v[5] = v1.y; v[6] = v1.z; v[7] = v1.w;
            }
            uint4 t0, t1;
            t0.x = cvt_tf32(v[0]); t0.y = cvt_tf32(v[1]);
            t0.z = cvt_tf32(v[2]); t0.w = cvt_tf32(v[3]);
            t1.x = cvt_tf32(v[4]); t1.y = cvt_tf32(v[5]);
            t1.z = cvt_tf32(v[6]); t1.w = cvt_tf32(v[7]);
            char* dst = smem + H2_AS + (uint32_t)arow_st * 144 + (uint32_t)akg * 4;
            *(uint4*)(dst) = t0;
            *(uint4*)(dst + 16) = t1;
        }
        __syncthreads();

#pragma unroll
        for (int ks = 0; ks < 4; ks++) {
            uint32_t a[4];
            ldsm4(a, smem_base + H2_AS + (uint32_t)(wm * 16 + arow) * 144
                     + acolb + (uint32_t)ks * 32);
            uint32_t b01[4], b23[4];
            uint32_t boff = (uint32_t)(wn * 32 + b_nrow) * 1040 + b_kb
                          + (uint32_t)(kc * 32 + ks * 8) * 4;
            ldsm4(b01, smem_base + H2_BS + boff);
            ldsm4(b23, smem_base + H2_BS + boff + 16 * 1040);
            uint32_t* bf[4] = {b01, b01 + 2, b23, b23 + 2};
#pragma unroll
            for (int nn = 0; nn < 4; nn++) mma_tf32(acc[nn], a, bf[nn]);
        }
        __syncthreads();
    }

    int erow = row0 + wm * 16 + (lane >> 2);
    int ecol = nbase + wn * 32 + (lane & 3) * 2;
#pragma unroll
    for (int nn = 0; nn < 4; nn++) {
        int c = ecol + nn * 8;
        float b0 = b2[c], b1 = b2[c + 1];
        if (erow < N_NODES) {
            float2 o = make_float2(fmaxf(acc[nn][0] + b0, 0.f),
                                   fmaxf(acc[nn][1] + b1, 0.f));
            *reinterpret_cast<float2*>(&g_h2[(size_t)erow * 128 + c]) = o;
        }
        if (erow + 8 < N_NODES) {
            float2 o = make_float2(fmaxf(acc[nn][2] + b0, 0.f),
                                   fmaxf(acc[nn][3] + b1, 0.f));
            *reinterpret_cast<float2*>(&g_h2[(size_t)(erow + 8) * 128 + c]) = o;
        }
    }
}

// ================= k_pq_tf32: p = h2@Wa, q = h2@Wb ============================
#define PQ_AS 0
#define PQ_BS 9216
#define PQ_TOTAL 43008

__global__ __launch_bounds__(256, 2)
void k_pq_tf32(const float* __restrict__ we1) {
    extern __shared__ __align__(16) char smem[];
    uint32_t smem_base = smem_u32(smem);
    int t = threadIdx.x, wid = t >> 5, lane = t & 31;
    int wm = wid >> 1;
    int wn = wid & 1;
    int row0 = blockIdx.x * 64;
    int qtr = blockIdx.y;
    int nbase = (qtr & 1) * 64;
    int krow0 = (qtr < 2) ? 0 : 128;

#pragma unroll 8
    for (int i = 0; i < 32; i++) {
        int idx = i * 256 + t;
        int k = idx >> 6, n = idx & 63;
        float w = we1[(krow0 + k) * 128 + nbase + n];
        *(uint32_t*)(smem + PQ_BS + (uint32_t)n * 528 + (uint32_t)k * 4) = cvt_tf32(w);
    }

    int arow_st = t >> 2;
    int akg = (t & 3) * 8;
    int grow_st = row0 + arow_st;
    bool valid = grow_st < N_NODES;

    int arow = lane & 15;
    uint32_t acolb = (lane & 16) ? 16u : 0u;
    int b_nrow = ((lane >> 4) << 3) + (lane & 7);
    uint32_t b_kb = ((lane >> 3) & 1) ? 16u : 0u;

    float acc[4][4] = {};

#pragma unroll 1
    for (int kc = 0; kc < 4; kc++) {
        {
            float v[8] = {0, 0, 0, 0, 0, 0, 0, 0};
            if (valid) {
                const float* src = &g_h2[(size_t)grow_st * 128 + kc * 32 + akg];
                float4 v0 = *reinterpret_cast<const float4*>(src);
                float4 v1 = *reinterpret_cast<const float4*>(src + 4);
                v[0] = v0.x; v[1] = v0.y; v[2] = v0.z; v[3] = v0.w;
                v[4] = v1.x; v[5] = v1.y; v[6] = v1.z; v[7] = v1.w;
            }
            uint4 t0, t1;
            t0.x = cvt_tf32(v[0]); t0.y = cvt_tf32(v[1]);
            t0.z = cvt_tf32(v[2]); t0.w = cvt_tf32(v[3]);
            t1.x = cvt_tf32(v[4]); t1.y = cvt_tf32(v[5]);
            t1.z = cvt_tf32(v[6]); t1.w = cvt_tf32(v[7]);
            char* dst = smem + PQ_AS + (uint32_t)arow_st * 144 + (uint32_t)akg * 4;
            *(uint4*)(dst) = t0;
            *(uint4*)(dst + 16) = t1;
        }
        __syncthreads();

#pragma unroll
        for (int ks = 0; ks < 4; ks++) {
            uint32_t a[4];
            ldsm4(a, smem_base + PQ_AS + (uint32_t)(wm * 16 + arow) * 144
                     + acolb + (uint32_t)ks * 32);
            uint32_t b01[4], b23[4];
            uint32_t boff = (uint32_t)(wn * 32 + b_nrow) * 528 + b_kb
                          + (uint32_t)(kc * 32 + ks * 8) * 4;
            ldsm4(b01, smem_base + PQ_BS + boff);
            ldsm4(b23, smem_base + PQ_BS + boff + 16 * 528);
            uint32_t* bf[4] = {b01, b01 + 2, b23, b23 + 2};
#pragma unroll
            for (int nn = 0; nn < 4; nn++) mma_tf32(acc[nn], a, bf[nn]);
        }
        __syncthreads();
    }

    float* dstg = (qtr < 2) ? g_p : g_q;
    int erow = row0 + wm * 16 + (lane >> 2);
    int ecol = nbase + wn * 32 + (lane & 3) * 2;
#pragma unroll
    for (int nn = 0; nn < 4; nn++) {
        int c = ecol + nn * 8;
        if (erow < N_NODES)
            *reinterpret_cast<float2*>(&dstg[(size_t)erow * 128 + c]) =
                make_float2(acc[nn][0], acc[nn][1]);
        if (erow + 8 < N_NODES)
            *reinterpret_cast<float2*>(&dstg[(size_t)(erow + 8) * 128 + c]) =
                make_float2(acc[nn][2], acc[nn][3]);
    }
}

// ================= edge MLP via tf32 mma (unchanged) ==========================
#define SM_A      0
#define SM_B      67584
#define SM_PA     101376
#define SM_PB     101888
#define SM_B2S    102400
#define SM_W3S    102656
#define SM_SRC    102912
#define SM_DST    103936
#define SM_EAS    104960
#define SM_EDGE_TOTAL 109056

#define N_TILES (N_EDGES / 128)
#define EDGE_GRID 296

__global__ __launch_bounds__(256, 2)
void k_edge_tf32(const int* __restrict__ ei, const float* __restrict__ ea,
                 const float* __restrict__ we1, const float* __restrict__ be1,
                 const float* __restrict__ we2, const float* __restrict__ be2,
                 const float* __restrict__ we3, const float* __restrict__ be3,
                 float* __restrict__ out) {
    extern __shared__ __align__(16) char smem[];
    uint32_t smem_base = smem_u32(smem);
    int t = threadIdx.x;
    int wid = t >> 5, lane = t & 31;
    int wm = wid >> 1;
    int wn = wid & 1;

    float* pa  = (float*)(smem + SM_PA);
    float* pb  = (float*)(smem + SM_PB);
    float* b2s = (float*)(smem + SM_B2S);
    float* w3s = (float*)(smem + SM_W3S);
    int*   srcs = (int*)(smem + SM_SRC);
    int*   dsts = (int*)(smem + SM_DST);
    float* eas  = (float*)(smem + SM_EAS);

    if (t < 64) { b2s[t] = be2[t]; w3s[t] = we3[t]; }

    int kq = lane * 4;
    float4 b1v = *reinterpret_cast<const float4*>(&be1[kq]);
    float4 wc0 = *reinterpret_cast<const float4*>(&we1[256 * 128 + kq]);
    float4 wc1 = *reinterpret_cast<const float4*>(&we1[257 * 128 + kq]);
    float4 wc2 = *reinterpret_cast<const float4*>(&we1[258 * 128 + kq]);
    float4 wc3 = *reinterpret_cast<const float4*>(&we1[259 * 128 + kq]);

    for (int idx = t; idx < 64 * 128; idx += 256) {
        int n = idx >> 7, k = idx & 127;
        uint32_t w = cvt_tf32(we2[k * 64 + n]);
        *(uint32_t*)(smem + SM_B + (uint32_t)n * 528 + (uint32_t)k * 4) = w;
    }
    float be3v = be3[0];

    int arow = lane & 15;
    uint32_t acolb = (lane & 16) ? 16u : 0u;
    int b_nrow = wn * 32 + ((lane >> 4) << 3) + (lane & 7);
    uint32_t b_kb = ((lane >> 3) & 1) ? 16u : 0u;
    uint32_t b_base = (uint32_t)b_nrow * 528 + b_kb;

    int tile = blockIdx.x;
    {
        int e0 = tile * 128;
        if (t < 128) srcs[t] = ei[e0 + t];
        else         dsts[t - 128] = ei[N_EDGES + e0 + (t - 128)];
        for (int i = t; i < 512; i += 256) eas[i] = ea[e0 * 4 + i];
    }
    __syncthreads();

    int buf = 0;
    for (; tile < N_TILES; tile += EDGE_GRID) {
        int e0 = tile * 128;
        int* sb = srcs + buf * 128;
        int* db = dsts + buf * 128;
        float* eb = eas + buf * 512;

#pragma unroll 4
        for (int i = 0; i < 16; i++) {
            int edge = i * 8 + wid;
            int s = sb[edge], d = db[edge];
            float4 pv = *reinterpret_cast<const float4*>(&g_p[s * 128 + kq]);
            float4 qv = *reinterpret_cast<const float4*>(&g_q[d * 128 + kq]);
            float4 e4 = *reinterpret_cast<const float4*>(&eb[edge * 4]);
            float v[4];
            v[0] = pv.x + qv.x + b1v.x + e4.x * wc0.x + e4.y * wc1.x + e4.z * wc2.x + e4.w * wc3.x;
            v[1] = pv.y + qv.y + b1v.y + e4.x * wc0.y + e4.y * wc1.y + e4.z * wc2.y + e4.w * wc3.y;
            v[2] = pv.z + qv.z + b1v.z + e4.x * wc0.z + e4.y * wc1.z + e4.z * wc2.z + e4.w * wc3.z;
            v[3] = pv.w + qv.w + b1v.w + e4.x * wc0.w + e4.y * wc1.w + e4.z * wc2.w + e4.w * wc3.w;
            uint4 tv;
            tv.x = cvt_tf32(fmaxf(v[0], 0.f));
            tv.y = cvt_tf32(fmaxf(v[1], 0.f));
            tv.z = cvt_tf32(fmaxf(v[2], 0.f));
            tv.w = cvt_tf32(fmaxf(v[3], 0.f));
            *(uint4*)(smem + SM_A + (uint32_t)edge * 528 + (uint32_t)kq * 4) = tv;
        }

        int nxt = tile + EDGE_GRID;
        if (nxt < N_TILES) {
            int e0n = nxt * 128;
            int* sn = srcs + (buf ^ 1) * 128;
            int* dn = dsts + (buf ^ 1) * 128;
            float* en = eas + (buf ^ 1) * 512;
            if (t < 128) sn[t] = ei[e0n + t];
            else         dn[t - 128] = ei[N_EDGES + e0n + (t - 128)];
            for (int i = t; i < 512; i += 256) en[i] = ea[e0n * 4 + i];
        }
        __syncthreads();

        float acc[2][4][4];
#pragma unroll
        for (int mi = 0; mi < 2; mi++)
#pragma unroll
            for (int nn = 0; nn < 4; nn++)
#pragma unroll
                for (int r = 0; r < 4; r++) acc[mi][nn][r] = 0.f;

#pragma unroll
        for (int kk = 0; kk < 16; kk++) {
            uint32_t a0[4], a1[4];
            uint32_t aoff = (uint32_t)(wm * 32 + arow) * 528 + acolb + (uint32_t)kk * 32;
            ldsm4(a0, smem_base + SM_A + aoff);
            ldsm4(a1, smem_base + SM_A + aoff + 16 * 528);

            uint32_t b01[4], b23[4];
            uint32_t boff = b_base + (uint32_t)kk * 32;
            ldsm4(b01, smem_base + SM_B + boff);
            ldsm4(b23, smem_base + SM_B + boff + 16 * 528);
            uint32_t* bf[4] = {b01, b01 + 2, b23, b23 + 2};

#pragma unroll
            for (int nn = 0; nn < 4; nn++) {
                mma_tf32(acc[0][nn], a0, bf[nn]);
                mma_tf32(acc[1][nn], a1, bf[nn]);
            }
        }

        float part[2][2] = {{0.f, 0.f}, {0.f, 0.f}};
#pragma unroll
        for (int mi = 0; mi < 2; mi++) {
#pragma unroll
            for (int nn = 0; nn < 4; nn++) {
                int c0 = wn * 32 + nn * 8 + (lane & 3) * 2;
                float w30 = w3s[c0], w31 = w3s[c0 + 1];
                float bb0 = b2s[c0], bb1 = b2s[c0 + 1];
                part[mi][0] += fmaxf(acc[mi][nn][0] + bb0, 0.f) * w30
                             + fmaxf(acc[mi][nn][1] + bb1, 0.f) * w31;
                part[mi][1] += fmaxf(acc[mi][nn][2] + bb0, 0.f) * w30
                             + fmaxf(acc[mi][nn][3] + bb1, 0.f) * w31;
            }
        }
#pragma unroll
        for (int mi = 0; mi < 2; mi++) {
#pragma unroll
            for (int g = 0; g < 2; g++) {
                part[mi][g] += __shfl_xor_sync(0xffffffffu, part[mi][g], 1);
                part[mi][g] += __shfl_xor_sync(0xffffffffu, part[mi][g], 2);
            }
        }
        if ((lane & 3) == 0) {
            float* pw = wn ? pb : pa;
            int r0 = wm * 32 + (lane >> 2);
            pw[r0]      = part[0][0];
            pw[r0 + 8]  = part[0][1];
            pw[r0 + 16] = part[1][0];
            pw[r0 + 24] = part[1][1];
        }
        __syncthreads();
        if (t < 128) out[e0 + t] = pa[t] + pb[t] + be3v;
        buf ^= 1;
    }
}

// ---------------- launch ----------------
extern "C" void kernel_launch(void* const* d_in, const int* in_sizes, int n_in,
                              void* d_out, int out_size) {
    const float* x   = (const float*)d_in[0];
    const int*   ei  = (const int*)d_in[1];
    const float* ea  = (const float*)d_in[2];
    const float* w1r = (const float*)d_in[3];
    const float* w1n = (const float*)d_in[4];
    const float* b1  = (const float*)d_in[5];
    const float* w2r = (const float*)d_in[6];
    const float* w2n = (const float*)d_in[7];
    const float* b2  = (const float*)d_in[8];
    const float* we1 = (const float*)d_in[9];
    const float* be1 = (const float*)d_in[10];
    const float* we2 = (const float*)d_in[11];
    const float* be2 = (const float*)d_in[12];
    const float* we3 = (const float*)d_in[13];
    const float* be3 = (const float*)d_in[14];
    float* out = (float*)d_out;

    cudaFuncSetAttribute(k_h2_tf32, cudaFuncAttributeMaxDynamicSharedMemorySize,
                         H2_TOTAL);
    cudaFuncSetAttribute(k_pq_tf32, cudaFuncAttributeMaxDynamicSharedMemorySize,
                         PQ_TOTAL);
    cudaFuncSetAttribute(k_edge_tf32, cudaFuncAttributeMaxDynamicSharedMemorySize,
                         SM_EDGE_TOTAL);

    // CSR build
    k_zero_deg<<<SCAN_B, 1024>>>();
    k_hist<<<N_EDGES / 256, 256>>>(ei);
    k_scan1<<<SCAN_B, 1024>>>();
    k_scan2<<<1, 128>>>();
    k_scan3<<<SCAN_B, 1024>>>();
    k_scatter<<<N_EDGES / 256, 256>>>(ei);
    // node pipeline
    k_h1g<<<N_NODES / 8, 256>>>(x, w1r, w1n, b1);
    k_gather2<<<N_NODES / 8, 256>>>();
    k_h2_tf32<<<dim3((N_NODES + 63) / 64, 2), 256, H2_TOTAL>>>(w2r, w2n, b2);
    k_pq_tf32<<<dim3((N_NODES + 63) / 64, 4), 256, PQ_TOTAL>>>(we1);
    // edge pipeline
    k_edge_tf32<<<EDGE_GRID, 256, SM_EDGE_TOTAL>>>(ei, ea, we1, be1, we2, be2, we3, be3, out);
}

// round 14
// speedup vs baseline: 1.6228x; 1.0400x over previous
#include <cuda_runtime.h>
#include <cuda_bf16.h>
#include <cstdint>

#define N_NODES 100000
#define N_EDGES 1600000
#define HID 128
#define SCAN_B 98                    // ceil(100000/1024)

// ---------------- scratch (device globals; no allocation) ----------------
__device__ int   g_deg [N_NODES];
__device__ int   g_off [N_NODES];
__device__ int   g_cur [N_NODES];
__device__ int   g_bsum[128];
__device__ int   g_elist[N_EDGES];   // src ids grouped by dst
__device__ int   g_dlist[N_EDGES];   // dst id per CSR position
__device__ int   g_eidl [N_EDGES];   // original edge id per CSR position
__device__ float g_h1  [N_NODES * HID];
__device__ float g_agg2[N_NODES * HID];   // mean of h1 over in-edges
__device__ float g_h2  [N_NODES * HID];
__device__ float g_p   [N_NODES * HID];
__device__ float g_q   [N_NODES * HID];

// ---------------- warp MMA helpers (baseline PTX) ----------------
__device__ __forceinline__ uint32_t smem_u32(const void* p) {
    uint32_t a;
    asm("{ .reg .u64 t; cvta.to.shared.u64 t, %1; cvt.u32.u64 %0, t; }" : "=r"(a) : "l"(p));
    return a;
}
__device__ __forceinline__ void mma_tf32(float* d, const uint32_t* a, const uint32_t* b) {
    asm volatile(
        "mma.sync.aligned.m16n8k8.row.col.f32.tf32.tf32.f32 "
        "{%0,%1,%2,%3}, {%4,%5,%6,%7}, {%8,%9}, {%0,%1,%2,%3};"
        : "+f"(d[0]), "+f"(d[1]), "+f"(d[2]), "+f"(d[3])
        : "r"(a[0]), "r"(a[1]), "r"(a[2]), "r"(a[3]), "r"(b[0]), "r"(b[1]));
}
__device__ __forceinline__ void ldsm4(uint32_t* r, uint32_t addr) {
    asm volatile("ldmatrix.sync.aligned.m8n8.x4.shared.b16 {%0,%1,%2,%3}, [%4];"
                 : "=r"(r[0]), "=r"(r[1]), "=r"(r[2]), "=r"(r[3]) : "r"(addr));
}
__device__ __forceinline__ uint32_t cvt_tf32(float x) {
    uint32_t u;
    asm("cvt.rna.tf32.f32 %0, %1;" : "=r"(u) : "f"(x));
    return u;
}

// ================== CSR build ==================
__global__ void k_zero_deg() {
    int i = blockIdx.x * 1024 + threadIdx.x;
    if (i < N_NODES) g_deg[i] = 0;
}
__global__ void k_hist(const int* __restrict__ ei) {
    int e = blockIdx.x * 256 + threadIdx.x;
    atomicAdd(&g_deg[ei[N_EDGES + e]], 1);
}
__global__ void k_scan1() {
    __shared__ int sh[1024];
    int tid = threadIdx.x;
    int i = blockIdx.x * 1024 + tid;
    int v = (i < N_NODES) ? g_deg[i] : 0;
    sh[tid] = v;
    __syncthreads();
#pragma unroll
    for (int ofs = 1; ofs < 1024; ofs <<= 1) {
        int o = (tid >= ofs) ? sh[tid - ofs] : 0;
        __syncthreads();
        sh[tid] += o;
        __syncthreads();
    }
    if (i < N_NODES) g_off[i] = sh[tid] - v;
    if (tid == 1023) g_bsum[blockIdx.x] = sh[1023];
}
__global__ void k_scan2() {
    __shared__ int sh[128];
    int t = threadIdx.x;
    int v = (t < SCAN_B) ? g_bsum[t] : 0;
    sh[t] = v;
    __syncthreads();
#pragma unroll
    for (int ofs = 1; ofs < 128; ofs <<= 1) {
        int o = (t >= ofs) ? sh[t - ofs] : 0;
        __syncthreads();
        sh[t] += o;
        __syncthreads();
    }
    if (t < SCAN_B) g_bsum[t] = sh[t] - v;
}
__global__ void k_scan3() {
    int i = blockIdx.x * 1024 + threadIdx.x;
    if (i < N_NODES) {
        int o = g_off[i] + g_bsum[blockIdx.x];
        g_off[i] = o;
        g_cur[i] = o;
    }
}
__global__ void k_scatter(const int* __restrict__ ei) {
    int e = blockIdx.x * 256 + threadIdx.x;
    int s = ei[e];
    int d = ei[N_EDGES + e];
    int pos = atomicAdd(&g_cur[d], 1);
    g_elist[pos] = s;
    g_dlist[pos] = d;
    g_eidl[pos] = e;
}

// ============ k_h1g: fused x-mean gather + h1 MLP (warp per node) ============
__global__ void k_h1g(const float* __restrict__ x,
                      const float* __restrict__ w1r, const float* __restrict__ w1n,
                      const float* __restrict__ b1) {
    int t = threadIdx.x;
    int lane = t & 31;
    int node = blockIdx.x * 8 + (t >> 5);

    float4 wr[6], wn[6];
#pragma unroll
    for (int k = 0; k < 6; k++) {
        wr[k] = *reinterpret_cast<const float4*>(&w1r[k * 128 + lane * 4]);
        wn[k] = *reinterpret_cast<const float4*>(&w1n[k * 128 + lane * 4]);
    }
    float4 bv = *reinterpret_cast<const float4*>(&b1[lane * 4]);

    int deg = g_deg[node];
    int off = g_off[node];

    float a0 = 0.f, a1 = 0.f, a2 = 0.f, a3 = 0.f, a4 = 0.f, a5 = 0.f;
    for (int i = lane; i < deg; i += 32) {
        int s = g_elist[off + i];
        const float2* xr = reinterpret_cast<const float2*>(x + s * 6);
        float2 v0 = xr[0], v1 = xr[1], v2 = xr[2];
        a0 += v0.x; a1 += v0.y; a2 += v1.x; a3 += v1.y; a4 += v2.x; a5 += v2.y;
    }
#pragma unroll
    for (int ofs = 16; ofs > 0; ofs >>= 1) {
        a0 += __shfl_xor_sync(0xffffffffu, a0, ofs);
        a1 += __shfl_xor_sync(0xffffffffu, a1, ofs);
        a2 += __shfl_xor_sync(0xffffffffu, a2, ofs);
        a3 += __shfl_xor_sync(0xffffffffu, a3, ofs);
        a4 += __shfl_xor_sync(0xffffffffu, a4, ofs);
        a5 += __shfl_xor_sync(0xffffffffu, a5, ofs);
    }
    float inv = 1.0f / fmaxf((float)deg, 1.0f);
    float m[6] = {a0 * inv, a1 * inv, a2 * inv, a3 * inv, a4 * inv, a5 * inv};

    const float2* xr = reinterpret_cast<const float2*>(x + node * 6);
    float2 x0 = xr[0], x1 = xr[1], x2 = xr[2];
    float xv[6] = {x0.x, x0.y, x1.x, x1.y, x2.x, x2.y};

    float4 h = bv;
#pragma unroll
    for (int k = 0; k < 6; k++) {
        h.x += xv[k] * wr[k].x + m[k] * wn[k].x;
        h.y += xv[k] * wr[k].y + m[k] * wn[k].y;
        h.z += xv[k] * wr[k].z + m[k] * wn[k].z;
        h.w += xv[k] * wr[k].w + m[k] * wn[k].w;
    }
    h.x = fmaxf(h.x, 0.f); h.y = fmaxf(h.y, 0.f);
    h.z = fmaxf(h.z, 0.f); h.w = fmaxf(h.w, 0.f);
    *reinterpret_cast<float4*>(&g_h1[(size_t)node * 128 + lane * 4]) = h;
}

// ============ k_gather2: mean of h1[srcs] -> g_agg2 (warp per node) ==========
__global__ void k_gather2() {
    int t = threadIdx.x;
    int lane = t & 31;
    int node = blockIdx.x * 8 + (t >> 5);
    int deg = g_deg[node];
    int off = g_off[node];

    float4 acc = make_float4(0.f, 0.f, 0.f, 0.f);
    int i = 0;
    for (; i + 4 <= deg; i += 4) {
        int s0 = g_elist[off + i + 0];
        int s1 = g_elist[off + i + 1];
        int s2 = g_elist[off + i + 2];
        int s3 = g_elist[off + i + 3];
        float4 v0 = *reinterpret_cast<const float4*>(&g_h1[(size_t)s0 * 128 + lane * 4]);
        float4 v1 = *reinterpret_cast<const float4*>(&g_h1[(size_t)s1 * 128 + lane * 4]);
        float4 v2 = *reinterpret_cast<const float4*>(&g_h1[(size_t)s2 * 128 + lane * 4]);
        float4 v3 = *reinterpret_cast<const float4*>(&g_h1[(size_t)s3 * 128 + lane * 4]);
        acc.x += v0.x + v1.x + v2.x + v3.x;
        acc.y += v0.y + v1.y + v2.y + v3.y;
        acc.z += v0.z + v1.z + v2.z + v3.z;
        acc.w += v0.w + v1.w + v2.w + v3.w;
    }
    for (; i < deg; i++) {
        int s = g_elist[off + i];
        float4 v = *reinterpret_cast<const float4*>(&g_h1[(size_t)s * 128 + lane * 4]);
        acc.x += v.x; acc.y += v.y; acc.z += v.z; acc.w += v.w;
    }
    float inv = 1.0f / fmaxf((float)deg, 1.0f);
    acc.x *= inv; acc.y *= inv; acc.z *= inv; acc.w *= inv;
    *reinterpret_cast<float4*>(&g_agg2[(size_t)node * 128 + lane * 4]) = acc;
}

// ================= k_h2_tf32: h2 = relu([h1|mean]@[W2r;W2n]+b2) ===============
#define H2_AS 0                       // 64*144   = 9216
#define H2_BS 9216                    // 64*1040  = 66560
#define H2_TOTAL 75776

__global__ __launch_bounds__(256, 2)
void k_h2_tf32(const float* __restrict__ w2r, const float* __restrict__ w2n,
               const float* __restrict__ b2) {
    extern __shared__ __align__(16) char smem[];
    uint32_t smem_base = smem_u32(smem);
    int t = threadIdx.x, wid = t >> 5, lane = t & 31;
    int wm = wid >> 1;
    int wn = wid & 1;
    int row0 = blockIdx.x * 64;
    int nbase = blockIdx.y * 64;

#pragma unroll 8
    for (int i = 0; i < 64; i++) {
        int idx = i * 256 + t;
        int k = idx >> 6, n = idx & 63;
        float w = (k < 128) ? w2r[k * 128 + nbase + n]
                            : w2n[(k - 128) * 128 + nbase + n];
        *(uint32_t*)(smem + H2_BS + (uint32_t)n * 1040 + (uint32_t)k * 4) = cvt_tf32(w);
    }

    int arow_st = t >> 2;
    int akg = (t & 3) * 8;
    int grow_st = row0 + arow_st;
    bool valid = grow_st < N_NODES;

    int arow = lane & 15;
    uint32_t acolb = (lane & 16) ? 16u : 0u;
    int b_nrow = ((lane >> 4) << 3) + (lane & 7);
    uint32_t b_kb = ((lane >> 3) & 1) ? 16u : 0u;

    float acc[4][4] = {};

#pragma unroll 1
    for (int kc = 0; kc < 8; kc++) {
        {
            float v[8] = {0, 0, 0, 0, 0, 0, 0, 0};
            if (valid) {
                const float* src = (kc < 4)
                    ? &g_h1[(size_t)grow_st * 128 + kc * 32 + akg]
                    : &g_agg2[(size_t)grow_st * 128 + (kc - 4) * 32 + akg];
                float4 v0 = *reinterpret_cast<const float4*>(src);
                float4 v1 = *reinterpret_cast<const float4*>(src + 4);
                v[0] = v0.x; v[1] = v0.y; v[2] = v0.z; v[3] = v0.w;
                v[4] = v1.x; v[5] = v1.y; v[6] = v1.z; v[7] = v1.w;
            }
            uint4 t0, t1;
            t0.x = cvt_tf32(v[0]); t0.y = cvt_tf32(v[1]);
            t0.z = cvt_tf32(v[2]); t0.w = cvt_tf32(v[3]);
            t1.x = cvt_tf32(v[4]); t1.y = cvt_tf32(v[5]);
            t1.z = cvt_tf32(v[6]); t1.w = cvt_tf32(v[7]);
            char* dst = smem + H2_AS + (uint32_t)arow_st * 144 + (uint32_t)akg * 4;
            *(uint4*)(dst) = t0;
            *(uint4*)(dst + 16) = t1;
        }
        __syncthreads();

#pragma unroll
        for (int ks = 0; ks < 4; ks++) {
            uint32_t a[4];
            ldsm4(a, smem_base + H2_AS + (uint32_t)(wm * 16 + arow) * 144
                     + acolb + (uint32_t)ks * 32);
            uint32_t b01[4], b23[4];
            uint32_t boff = (uint32_t)(wn * 32 + b_nrow) * 1040 + b_kb
                          + (uint32_t)(kc * 32 + ks * 8) * 4;
            ldsm4(b01, smem_base + H2_BS + boff);
            ldsm4(b23, smem_base + H2_BS + boff + 16 * 1040);
            uint32_t* bf[4] = {b01, b01 + 2, b23, b23 + 2};
#pragma unroll
            for (int nn = 0; nn < 4; nn++) mma_tf32(acc[nn], a, bf[nn]);
        }
        __syncthreads();
    }

    int erow = row0 + wm * 16 + (lane >> 2);
    int ecol = nbase + wn * 32 + (lane & 3) * 2;
#pragma unroll
    for (int nn = 0; nn < 4; nn++) {
        int c = ecol + nn * 8;
        float b0 = b2[c], b1 = b2[c + 1];
        if (erow < N_NODES) {
            float2 o = make_float2(fmaxf(acc[nn][0] + b0, 0.f),
                                   fmaxf(acc[nn][1] + b1, 0.f));
            *reinterpret_cast<float2*>(&g_h2[(size_t)erow * 128 + c]) = o;
        }
        if (erow + 8 < N_NODES) {
            float2 o = make_float2(fmaxf(acc[nn][2] + b0, 0.f),
                                   fmaxf(acc[nn][3] + b1, 0.f));
            *reinterpret_cast<float2*>(&g_h2[(size_t)(erow + 8) * 128 + c]) = o;
        }
    }
}

// ================= k_pq_tf32: p = h2@Wa, q = h2@Wb ============================
#define PQ_AS 0
#define PQ_BS 9216
#define PQ_TOTAL 43008

__global__ __launch_bounds__(256, 2)
void k_pq_tf32(const float* __restrict__ we1) {
    extern __shared__ __align__(16) char smem[];
    uint32_t smem_base = smem_u32(smem);
    int t = threadIdx.x, wid = t >> 5, lane = t & 31;
    int wm = wid >> 1;
    int wn = wid & 1;
    int row0 = blockIdx.x * 64;
    int qtr = blockIdx.y;
    int nbase = (qtr & 1) * 64;
    int krow0 = (qtr < 2) ? 0 : 128;

#pragma unroll 8
    for (int i = 0; i < 32; i++) {
        int idx = i * 256 + t;
        int k = idx >> 6, n = idx & 63;
        float w = we1[(krow0 + k) * 128 + nbase + n];
        *(uint32_t*)(smem + PQ_BS + (uint32_t)n * 528 + (uint32_t)k * 4) = cvt_tf32(w);
    }

    int arow_st = t >> 2;
    int akg = (t & 3) * 8;
    int grow_st = row0 + arow_st;
    bool valid = grow_st < N_NODES;

    int arow = lane & 15;
    uint32_t acolb = (lane & 16) ? 16u : 0u;
    int b_nrow = ((lane >> 4) << 3) + (lane & 7);
    uint32_t b_kb = ((lane >> 3) & 1) ? 16u : 0u;

    float acc[4][4] = {};

#pragma unroll 1
    for (int kc = 0; kc < 4; kc++) {
        {
            float v[8] = {0, 0, 0, 0, 0, 0, 0, 0};
            if (valid) {
                const float* src = &g_h2[(size_t)grow_st * 128 + kc * 32 + akg];
                float4 v0 = *reinterpret_cast<const float4*>(src);
                float4 v1 = *reinterpret_cast<const float4*>(src + 4);
                v[0] = v0.x; v[1] = v0.y; v[2] = v0.z; v[3] = v0.w;
                v[4] = v1.x; v[5] = v1.y; v[6] = v1.z; v[7] = v1.w;
            }
            uint4 t0, t1;
            t0.x = cvt_tf32(v[0]); t0.y = cvt_tf32(v[1]);
            t0.z = cvt_tf32(v[2]); t0.w = cvt_tf32(v[3]);
            t1.x = cvt_tf32(v[4]); t1.y = cvt_tf32(v[5]);
            t1.z = cvt_tf32(v[6]); t1.w = cvt_tf32(v[7]);
            char* dst = smem + PQ_AS + (uint32_t)arow_st * 144 + (uint32_t)akg * 4;
            *(uint4*)(dst) = t0;
            *(uint4*)(dst + 16) = t1;
        }
        __syncthreads();

#pragma unroll
        for (int ks = 0; ks < 4; ks++) {
            uint32_t a[4];
            ldsm4(a, smem_base + PQ_AS + (uint32_t)(wm * 16 + arow) * 144
                     + acolb + (uint32_t)ks * 32);
            uint32_t b01[4], b23[4];
            uint32_t boff = (uint32_t)(wn * 32 + b_nrow) * 528 + b_kb
                          + (uint32_t)(kc * 32 + ks * 8) * 4;
            ldsm4(b01, smem_base + PQ_BS + boff);
            ldsm4(b23, smem_base + PQ_BS + boff + 16 * 528);
            uint32_t* bf[4] = {b01, b01 + 2, b23, b23 + 2};
#pragma unroll
            for (int nn = 0; nn < 4; nn++) mma_tf32(acc[nn], a, bf[nn]);
        }
        __syncthreads();
    }

    float* dstg = (qtr < 2) ? g_p : g_q;
    int erow = row0 + wm * 16 + (lane >> 2);
    int ecol = nbase + wn * 32 + (lane & 3) * 2;
#pragma unroll
    for (int nn = 0; nn < 4; nn++) {
        int c = ecol + nn * 8;
        if (erow < N_NODES)
            *reinterpret_cast<float2*>(&dstg[(size_t)erow * 128 + c]) =
                make_float2(acc[nn][0], acc[nn][1]);
        if (erow + 8 < N_NODES)
            *reinterpret_cast<float2*>(&dstg[(size_t)(erow + 8) * 128 + c]) =
                make_float2(acc[nn][2], acc[nn][3]);
    }
}

// ========== edge MLP via tf32 mma, CSR (dst-grouped) edge order ===============
// Consecutive CSR positions share dst -> q[dst] rows are L1-resident.
// out[eid] scattered; ea gathered by eid. Per-edge math identical to R12.
#define SM_A      0
#define SM_B      67584
#define SM_PA     101376
#define SM_PB     101888
#define SM_B2S    102400
#define SM_W3S    102656
#define SM_SRC    102912              // int[2][128]
#define SM_DST    103936              // int[2][128]
#define SM_EID    104960              // int[2][128]
#define SM_EAS    105984              // float[2][512]
#define SM_EDGE_TOTAL 110080

#define N_TILES (N_EDGES / 128)
#define EDGE_GRID 296

__global__ __launch_bounds__(256, 2)
void k_edge_tf32(const float* __restrict__ ea,
                 const float* __restrict__ we1, const float* __restrict__ be1,
                 const float* __restrict__ we2, const float* __restrict__ be2,
                 const float* __restrict__ we3, const float* __restrict__ be3,
                 float* __restrict__ out) {
    extern __shared__ __align__(16) char smem[];
    uint32_t smem_base = smem_u32(smem);
    int t = threadIdx.x;
    int wid = t >> 5, lane = t & 31;
    int wm = wid >> 1;
    int wn = wid & 1;

    float* pa  = (float*)(smem + SM_PA);
    float* pb  = (float*)(smem + SM_PB);
    float* b2s = (float*)(smem + SM_B2S);
    float* w3s = (float*)(smem + SM_W3S);
    int*   srcs = (int*)(smem + SM_SRC);
    int*   dsts = (int*)(smem + SM_DST);
    int*   eids = (int*)(smem + SM_EID);
    float* eas  = (float*)(smem + SM_EAS);

    if (t < 64) { b2s[t] = be2[t]; w3s[t] = we3[t]; }

    int kq = lane * 4;
    float4 b1v = *reinterpret_cast<const float4*>(&be1[kq]);
    float4 wc0 = *reinterpret_cast<const float4*>(&we1[256 * 128 + kq]);
    float4 wc1 = *reinterpret_cast<const float4*>(&we1[257 * 128 + kq]);
    float4 wc2 = *reinterpret_cast<const float4*>(&we1[258 * 128 + kq]);
    float4 wc3 = *reinterpret_cast<const float4*>(&we1[259 * 128 + kq]);

    for (int idx = t; idx < 64 * 128; idx += 256) {
        int n = idx >> 7, k = idx & 127;
        uint32_t w = cvt_tf32(we2[k * 64 + n]);
        *(uint32_t*)(smem + SM_B + (uint32_t)n * 528 + (uint32_t)k * 4) = w;
    }
    float be3v = be3[0];

    int arow = lane & 15;
    uint32_t acolb = (lane & 16) ? 16u : 0u;
    int b_nrow = wn * 32 + ((lane >> 4) << 3) + (lane & 7);
    uint32_t b_kb = ((lane >> 3) & 1) ? 16u : 0u;
    uint32_t b_base = (uint32_t)b_nrow * 528 + b_kb;

    int tile = blockIdx.x;
    {
        int e0 = tile * 128;
        if (t < 128) {
            srcs[t] = g_elist[e0 + t];
            int eid = g_eidl[e0 + t];
            eids[t] = eid;
            *reinterpret_cast<float4*>(&eas[t * 4]) =
                *reinterpret_cast<const float4*>(&ea[(size_t)eid * 4]);
        } else {
            dsts[t - 128] = g_dlist[e0 + (t - 128)];
        }
    }
    __syncthreads();

    int buf = 0;
    for (; tile < N_TILES; tile += EDGE_GRID) {
        int* sb = srcs + buf * 128;
        int* db = dsts + buf * 128;
        int* eb_id = eids + buf * 128;
        float* eb = eas + buf * 512;

        // ---- gather (float4, warp-per-edge) + e1 + cvt.tf32 into smem A ----
#pragma unroll 4
        for (int i = 0; i < 16; i++) {
            int edge = i * 8 + wid;
            int s = sb[edge], d = db[edge];
            float4 pv = *reinterpret_cast<const float4*>(&g_p[(size_t)s * 128 + kq]);
            float4 qv = *reinterpret_cast<const float4*>(&g_q[(size_t)d * 128 + kq]);
            float4 e4 = *reinterpret_cast<const float4*>(&eb[edge * 4]);
            float v[4];
            v[0] = pv.x + qv.x + b1v.x + e4.x * wc0.x + e4.y * wc1.x + e4.z * wc2.x + e4.w * wc3.x;
            v[1] = pv.y + qv.y + b1v.y + e4.x * wc0.y + e4.y * wc1.y + e4.z * wc2.y + e4.w * wc3.y;
            v[2] = pv.z + qv.z + b1v.z + e4.x * wc0.z + e4.y * wc1.z + e4.z * wc2.z + e4.w * wc3.z;
            v[3] = pv.w + qv.w + b1v.w + e4.x * wc0.w + e4.y * wc1.w + e4.z * wc2.w + e4.w * wc3.w;
            uint4 tv;
            tv.x = cvt_tf32(fmaxf(v[0], 0.f));
            tv.y = cvt_tf32(fmaxf(v[1], 0.f));
            tv.z = cvt_tf32(fmaxf(v[2], 0.f));
            tv.w = cvt_tf32(fmaxf(v[3], 0.f));
            *(uint4*)(smem + SM_A + (uint32_t)edge * 528 + (uint32_t)kq * 4) = tv;
        }

        // ---- stage next tile into other buffer (overlaps with gather) ----
        int nxt = tile + EDGE_GRID;
        if (nxt < N_TILES) {
            int e0n = nxt * 128;
            int* sn = srcs + (buf ^ 1) * 128;
            int* dn = dsts + (buf ^ 1) * 128;
            int* en_id = eids + (buf ^ 1) * 128;
            float* en = eas + (buf ^ 1) * 512;
            if (t < 128) {
                sn[t] = g_elist[e0n + t];
                int eid = g_eidl[e0n + t];
                en_id[t] = eid;
                *reinterpret_cast<float4*>(&en[t * 4]) =
                    *reinterpret_cast<const float4*>(&ea[(size_t)eid * 4]);
            } else {
                dn[t - 128] = g_dlist[e0n + (t - 128)];
            }
        }
        __syncthreads();

        float acc[2][4][4];
#pragma unroll
        for (int mi = 0; mi < 2; mi++)
#pragma unroll
            for (int nn = 0; nn < 4; nn++)
#pragma unroll
                for (int r = 0; r < 4; r++) acc[mi][nn][r] = 0.f;

#pragma unroll
        for (int kk = 0; kk < 16; kk++) {
            uint32_t a0[4], a1[4];
            uint32_t aoff = (uint32_t)(wm * 32 + arow) * 528 + acolb + (uint32_t)kk * 32;
            ldsm4(a0, smem_base + SM_A + aoff);
            ldsm4(a1, smem_base + SM_A + aoff + 16 * 528);

            uint32_t b01[4], b23[4];
            uint32_t boff = b_base + (uint32_t)kk * 32;
            ldsm4(b01, smem_base + SM_B + boff);
            ldsm4(b23, smem_base + SM_B + boff + 16 * 528);
            uint32_t* bf[4] = {b01, b01 + 2, b23, b23 + 2};

#pragma unroll
            for (int nn = 0; nn < 4; nn++) {
                mma_tf32(acc[0][nn], a0, bf[nn]);
                mma_tf32(acc[1][nn], a1, bf[nn]);
            }
        }

        float part[2][2] = {{0.f, 0.f}, {0.f, 0.f}};
#pragma unroll
        for (int mi = 0; mi < 2; mi++) {
#pragma unroll
            for (int nn = 0; nn < 4; nn++) {
                int c0 = wn * 32 + nn * 8 + (lane & 3) * 2;
                float w30 = w3s[c0], w31 = w3s[c0 + 1];
                float bb0 = b2s[c0], bb1 = b2s[c0 + 1];
                part[mi][0] += fmaxf(acc[mi][nn][0] + bb0, 0.f) * w30
                             + fmaxf(acc[mi][nn][1] + bb1, 0.f) * w31;
                part[mi][1] += fmaxf(acc[mi][nn][2] + bb0, 0.f) * w30
                             + fmaxf(acc[mi][nn][3] + bb1, 0.f) * w31;
            }
        }
#pragma unroll
        for (int mi = 0; mi < 2; mi++) {
#pragma unroll
            for (int g = 0; g < 2; g++) {
                part[mi][g] += __shfl_xor_sync(0xffffffffu, part[mi][g], 1);
                part[mi][g] += __shfl_xor_sync(0xffffffffu, part[mi][g], 2);
            }
        }
        if ((lane & 3) == 0) {
            float* pw = wn ? pb : pa;
            int r0 = wm * 32 + (lane >> 2);
            pw[r0]      = part[0][0];
            pw[r0 + 8]  = part[0][1];
            pw[r0 + 16] = part[1][0];
            pw[r0 + 24] = part[1][1];
        }
        __syncthreads();
        if (t < 128) out[eb_id[t]] = pa[t] + pb[t] + be3v;
        buf ^= 1;
    }
}

// ---------------- launch ----------------
extern "C" void kernel_launch(void* const* d_in, const int* in_sizes, int n_in,
                              void* d_out, int out_size) {
    const float* x   = (const float*)d_in[0];
    const int*   ei  = (const int*)d_in[1];
    const float* ea  = (const float*)d_in[2];
    const float* w1r = (const float*)d_in[3];
    const float* w1n = (const float*)d_in[4];
    const float* b1  = (const float*)d_in[5];
    const float* w2r = (const float*)d_in[6];
    const float* w2n = (const float*)d_in[7];
    const float* b2  = (const float*)d_in[8];
    const float* we1 = (const float*)d_in[9];
    const float* be1 = (const float*)d_in[10];
    const float* we2 = (const float*)d_in[11];
    const float* be2 = (const float*)d_in[12];
    const float* we3 = (const float*)d_in[13];
    const float* be3 = (const float*)d_in[14];
    float* out = (float*)d_out;

    cudaFuncSetAttribute(k_h2_tf32, cudaFuncAttributeMaxDynamicSharedMemorySize,
                         H2_TOTAL);
    cudaFuncSetAttribute(k_pq_tf32, cudaFuncAttributeMaxDynamicSharedMemorySize,
                         PQ_TOTAL);
    cudaFuncSetAttribute(k_edge_tf32, cudaFuncAttributeMaxDynamicSharedMemorySize,
                         SM_EDGE_TOTAL);

    // CSR build
    k_zero_deg<<<SCAN_B, 1024>>>();
    k_hist<<<N_EDGES / 256, 256>>>(ei);
    k_scan1<<<SCAN_B, 1024>>>();
    k_scan2<<<1, 128>>>();
    k_scan3<<<SCAN_B, 1024>>>();
    k_scatter<<<N_EDGES / 256, 256>>>(ei);
    // node pipeline
    k_h1g<<<N_NODES / 8, 256>>>(x, w1r, w1n, b1);
    k_gather2<<<N_NODES / 8, 256>>>();
    k_h2_tf32<<<dim3((N_NODES + 63) / 64, 2), 256, H2_TOTAL>>>(w2r, w2n, b2);
    k_pq_tf32<<<dim3((N_NODES + 63) / 64, 4), 256, PQ_TOTAL>>>(we1);
    // edge pipeline
    k_edge_tf32<<<EDGE_GRID, 256, SM_EDGE_TOTAL>>>(ea, we1, be1, we2, be2, we3, be3, out);
}